// round 12
// baseline (speedup 1.0000x reference)
#include <cuda_runtime.h>

#define Hd 64
#define Vd 64
#define INNER 24
#define SEQ 32
#define CAP 8
#define NPAIR 15
#define LRc 0.05f
#define B1c 0.9f
#define B2c 0.999f
#define EPSc 1e-8f

#define NW1 (Hd*INNER)             // 1536
#define OFF_B1 NW1                 // 1536
#define OFF_W2 (NW1 + INNER)       // 1560
#define OFF_B2 (OFF_W2 + INNER*Hd) // 3096
#define NPARAM (OFF_B2 + Hd)       // 3160

typedef unsigned long long ull;

// Packed fp32x2 ops (sm_103a FFMA2 path — per-lane IEEE fp32, bit-identical)
#define PACKF2(d, lo, hi) asm("mov.b64 %0, {%1, %2};" : "=l"(d) : "f"(lo), "f"(hi))
#define UNPACKF2(lo, hi, s) asm("mov.b64 {%0, %1}, %2;" : "=f"(lo), "=f"(hi) : "l"(s))
#define FMAF2(d, a, b, c) asm("fma.rn.f32x2 %0, %1, %2, %3;" : "=l"(d) : "l"(a), "l"(b), "l"(c))
#define MULF2(d, a, b) asm("mul.rn.f32x2 %0, %1, %2;" : "=l"(d) : "l"(a), "l"(b))

struct __align__(16) SmemLayout {
    float h[SEQ*Hd];               // 2048 floats (8KB)
    union {
        ull scratch[4096];         // encode-only: SPLATTED hidden acts (4 warps x 1024, 32KB)
        struct {
            float P[NPARAM];       // params  w1[i*24+j] | b1 | w2[j*64+o] | b2
            float a1[INNER];       // 16B-aligned (P is 12640B)
            float dz1[INNER];
            float dout[Hd];
            float scores[NPAIR + 1];
            float esc[CAP];
            int   ord[CAP];
            int   toks[SEQ];       // only live before encode (pre-scratch)
        };
    };
};

__device__ __forceinline__ float wredsum(float x) {
    #pragma unroll
    for (int o = 16; o; o >>= 1) x += __shfl_xor_sync(0xffffffffu, x, o);
    return x;
}

// Exact eps-folded Adam on a quad; m/v state PACKED in registers, params in smem.
__device__ __forceinline__ void adam4p(float4* __restrict__ P4, int f,
                                       ull& mL, ull& mH, ull& vL, ull& vH,
                                       ull gL, ull gH, float negC, float epsT,
                                       ull cB1, ull c01, ull cB2, ull c001) {
    ull t;
    MULF2(t, c01, gL);  FMAF2(mL, cB1, mL, t);
    MULF2(t, c01, gH);  FMAF2(mH, cB1, mH, t);
    MULF2(t, c001, gL); MULF2(t, t, gL); FMAF2(vL, cB2, vL, t);
    MULF2(t, c001, gH); MULF2(t, t, gH); FMAF2(vH, cB2, vH, t);
    float v0, v1, v2, v3, m0, m1, m2, m3;
    UNPACKF2(v0, v1, vL); UNPACKF2(v2, v3, vH);
    UNPACKF2(m0, m1, mL); UNPACKF2(m2, m3, mH);
    float s0 = fmaxf(v0 * __frsqrt_rn(v0), 0.0f);
    float s1 = fmaxf(v1 * __frsqrt_rn(v1), 0.0f);
    float s2_ = fmaxf(v2 * __frsqrt_rn(v2), 0.0f);
    float s3 = fmaxf(v3 * __frsqrt_rn(v3), 0.0f);
    float4 p = P4[f];
    p.x = fmaf(negC, __fdividef(m0, s0 + epsT), p.x);
    p.y = fmaf(negC, __fdividef(m1, s1 + epsT), p.y);
    p.z = fmaf(negC, __fdividef(m2, s2_ + epsT), p.z);
    p.w = fmaf(negC, __fdividef(m3, s3 + epsT), p.w);
    P4[f] = p;
}

__global__ void __launch_bounds__(128, 4) ttt_kernel(
    const int*   __restrict__ seqs,
    const float* __restrict__ embed,
    const float* __restrict__ ffw1, const float* __restrict__ ffb1,
    const float* __restrict__ ffw2, const float* __restrict__ ffb2,
    const float* __restrict__ lng,  const float* __restrict__ lnb,
    const float* __restrict__ scw,  const float* __restrict__ scb,
    const float* __restrict__ mw1,  const float* __restrict__ mb1,
    const float* __restrict__ mw2,  const float* __restrict__ mb2,
    const float* __restrict__ outw, const float* __restrict__ outb,
    float* __restrict__ out)
{
    __shared__ SmemLayout s;
    const int tid  = threadIdx.x;
    const int lane = tid & 31;
    const int w    = tid >> 5;
    const int b    = blockIdx.x;

    // ---- tokens + embeddings (float4) ----
    if (tid < SEQ) s.toks[tid] = seqs[b * SEQ + tid];
    __syncthreads();
    {
        const float4* e4 = (const float4*)embed;
        float4* h4 = (float4*)s.h;
        #pragma unroll
        for (int r = 0; r < 4; r++) {
            int idx = tid + 128 * r;          // 0..511
            int t = idx >> 4, c = idx & 15;
            h4[idx] = e4[s.toks[t] * 16 + c];
        }
    }
    __syncthreads();

    // ---- encode: warp w handles tokens {w, w+4, ..., w+28} ----
    {
        // layer 1 (PACKED f32x2): lane owns cols [4*lane, 4*lane+4)
        const ulonglong2* w1_p = (const ulonglong2*)ffw1;
        ulonglong2 bbp = ((const ulonglong2*)ffb1)[lane];
        ull accL[8], accH[8];
        #pragma unroll
        for (int tk = 0; tk < 8; tk++) { accL[tk] = bbp.x; accH[tk] = bbp.y; }
        #pragma unroll 2
        for (int ib = 0; ib < Hd; ib += 4) {
            ulonglong2 wv0 = w1_p[(ib + 0) * 32 + lane];
            ulonglong2 wv1 = w1_p[(ib + 1) * 32 + lane];
            ulonglong2 wv2 = w1_p[(ib + 2) * 32 + lane];
            ulonglong2 wv3 = w1_p[(ib + 3) * 32 + lane];
            #pragma unroll
            for (int tk = 0; tk < 8; tk++) {
                float4 ev = *(const float4*)&s.h[(w + 4 * tk) * Hd + ib];
                ull e;
                PACKF2(e, ev.x, ev.x);
                FMAF2(accL[tk], e, wv0.x, accL[tk]);
                FMAF2(accH[tk], e, wv0.y, accH[tk]);
                PACKF2(e, ev.y, ev.y);
                FMAF2(accL[tk], e, wv1.x, accL[tk]);
                FMAF2(accH[tk], e, wv1.y, accH[tk]);
                PACKF2(e, ev.z, ev.z);
                FMAF2(accL[tk], e, wv2.x, accL[tk]);
                FMAF2(accH[tk], e, wv2.y, accH[tk]);
                PACKF2(e, ev.w, ev.w);
                FMAF2(accL[tk], e, wv3.x, accL[tk]);
                FMAF2(accH[tk], e, wv3.y, accH[tk]);
            }
        }
        // relu + store SPLATTED (each act duplicated into both f32x2 lanes)
        #pragma unroll
        for (int tk = 0; tk < 8; tk++) {
            float a0, a1_, a2_, a3;
            UNPACKF2(a0, a1_, accL[tk]);
            UNPACKF2(a2_, a3, accH[tk]);
            a0 = fmaxf(a0, 0.0f); a1_ = fmaxf(a1_, 0.0f);
            a2_ = fmaxf(a2_, 0.0f); a3 = fmaxf(a3, 0.0f);
            ull p0, p1, p2, p3;
            PACKF2(p0, a0, a0); PACKF2(p1, a1_, a1_);
            PACKF2(p2, a2_, a2_); PACKF2(p3, a3, a3);
            ulonglong2 q0; q0.x = p0; q0.y = p1;
            ulonglong2 q1; q1.x = p2; q1.y = p3;
            *(ulonglong2*)&s.scratch[w * 1024 + tk * 128 + 4 * lane]     = q0;
            *(ulonglong2*)&s.scratch[w * 1024 + tk * 128 + 4 * lane + 2] = q1;
        }
        __syncwarp();

        // layer 2 (FULLY PACKED, pre-splatted acts): lane owns cols [2*lane, 2*lane+2)
        const ull* w2u = (const ull*)ffw2;
        ull accp[8];
        ull fbp = ((const ull*)ffb2)[lane];
        #pragma unroll
        for (int tk = 0; tk < 8; tk++) accp[tk] = fbp;
        #pragma unroll 2
        for (int ib = 0; ib < 2 * Hd; ib += 4) {
            ull wv0 = w2u[(ib + 0) * 32 + lane];
            ull wv1 = w2u[(ib + 1) * 32 + lane];
            ull wv2 = w2u[(ib + 2) * 32 + lane];
            ull wv3 = w2u[(ib + 3) * 32 + lane];
            #pragma unroll
            for (int tk = 0; tk < 8; tk++) {
                ulonglong2 e01 = *(const ulonglong2*)&s.scratch[w * 1024 + tk * 128 + ib];
                ulonglong2 e23 = *(const ulonglong2*)&s.scratch[w * 1024 + tk * 128 + ib + 2];
                FMAF2(accp[tk], e01.x, wv0, accp[tk]);
                FMAF2(accp[tk], e01.y, wv1, accp[tk]);
                FMAF2(accp[tk], e23.x, wv2, accp[tk]);
                FMAF2(accp[tk], e23.y, wv3, accp[tk]);
            }
        }

        // residual + layernorm
        float2 g2  = ((const float2*)lng)[lane];
        float2 be2 = ((const float2*)lnb)[lane];
        float2* h2 = (float2*)s.h;
        #pragma unroll
        for (int tk = 0; tk < 8; tk++) {
            int t = w + 4 * tk;
            float f0, f1;
            UNPACKF2(f0, f1, accp[tk]);
            float2 x = h2[t * 32 + lane];
            x.x += f0; x.y += f1;
            float mean = wredsum(x.x + x.y) * (1.0f / 64.0f);
            float d0 = x.x - mean, d1 = x.y - mean;
            float var = wredsum(d0 * d0 + d1 * d1) * (1.0f / 64.0f);
            float rs = rsqrtf(var + 1e-5f);
            float2 r;
            r.x = fmaf(d0 * rs, g2.x, be2.x);
            r.y = fmaf(d1 * rs, g2.y, be2.y);
            h2[t * 32 + lane] = r;
        }
    }
    __syncthreads();

    // ---- scores (scratch dead from here; P/a1/... region live) ----
    for (int p = w; p < NPAIR; p += 4) {
        const float* kk = &s.h[(2 * p)     * Hd];
        const float* vv = &s.h[(2 * p + 1) * Hd];
        float acc = kk[lane]      * scw[lane]
                  + kk[lane + 32] * scw[lane + 32]
                  + vv[lane]      * scw[lane + 64]
                  + vv[lane + 32] * scw[lane + 96];
        acc = wredsum(acc);
        if (lane == 0) s.scores[p] = acc + scb[0];
    }
    __syncthreads();

    // ---- evict-min (thread 0) overlapped with P init (all) ----
    if (tid == 0) {
        #pragma unroll
        for (int i = 0; i < CAP; i++) { s.ord[i] = i; s.esc[i] = s.scores[i]; }
        for (int n = CAP; n < NPAIR; n++) {
            int mi = 0; float mv = s.esc[0];
            #pragma unroll
            for (int i = 1; i < CAP; i++) if (s.esc[i] < mv) { mv = s.esc[i]; mi = i; }
            for (int i = mi; i < CAP - 1; i++) { s.ord[i] = s.ord[i+1]; s.esc[i] = s.esc[i+1]; }
            s.ord[CAP-1] = n; s.esc[CAP-1] = s.scores[n];
        }
    }
    {
        float4* P4 = (float4*)s.P;
        for (int q = tid; q < 384; q += 128) P4[q]       = ((const float4*)mw1)[q];
        for (int q = tid; q < 384; q += 128) P4[390 + q] = ((const float4*)mw2)[q];
        if (tid < 6)  P4[384 + tid] = ((const float4*)mb1)[tid];
        if (tid >= 32 && tid < 48) P4[774 + (tid - 32)] = ((const float4*)mb2)[tid - 32];
    }
    __syncthreads();

    // per-thread constant index seeds for the w1 float4 update loop
    const int q0 = 4 * tid;
    const int j0 = q0 % 24;     // multiple of 4, row never crossed (24 % 4 == 0)
    const int i0 = q0 / 24;

    // packed Adam constants
    ull cB1, c01, cB2, c001;
    PACKF2(cB1, B1c, B1c);
    PACKF2(c01, 0.1f, 0.1f);
    PACKF2(cB2, B2c, B2c);
    PACKF2(c001, 0.001f, 0.001f);

    // ---- Adam state PACKED in registers (same param indices every step) ----
    ull mW1L[3], mW1H[3], vW1L[3], vW1H[3];
    ull mW2L[3], mW2H[3], vW2L[3], vW2H[3];
    ull mBL = 0, mBH = 0, vBL = 0, vBH = 0;
    #pragma unroll
    for (int k = 0; k < 3; k++) {
        mW1L[k] = mW1H[k] = vW1L[k] = vW1H[k] = 0;
        mW2L[k] = mW2H[k] = vW2L[k] = vW2H[k] = 0;
    }

    // ---- 8 inner Adam steps ----
    float pb1 = 1.0f, pb2 = 1.0f;
    #pragma unroll 1
    for (int st = 0; st < CAP; st++) {
        pb1 *= B1c; pb2 *= B2c;
        float inv1 = __fdividef(1.0f, 1.0f - pb1);
        float s2   = sqrtf(1.0f - pb2);
        float negC = -LRc * inv1 * s2;
        float epsT = EPSc * s2;
        int koff = (s.ord[st] << 1) * Hd;
        int voff = koff + Hd;

        // fwd layer1: 96 threads, 4 lanes per j
        if (tid < 96) {
            const int j  = ((tid >> 5) << 3) + ((tid & 31) >> 2);
            const int sl = tid & 3;
            float acc = 0.0f;
            #pragma unroll
            for (int k = 0; k < 16; k++)
                acc = fmaf(s.h[koff + sl + 4 * k], s.P[(sl + 4 * k) * INNER + j], acc);
            acc += __shfl_xor_sync(0xffffffffu, acc, 1);
            acc += __shfl_xor_sync(0xffffffffu, acc, 2);
            if (sl == 0) s.a1[j] = fmaxf(acc + s.P[OFF_B1 + j], 0.0f);
        }
        __syncthreads();

        // fwd layer2 + output grad: 64 threads, 1 lane per o, conflict-free,
        // two chains summed in the same order as the old shfl pair (bit-identical)
        if (tid < 64) {
            const int o = tid;
            float accA = 0.0f, accB = 0.0f;
            #pragma unroll
            for (int k = 0; k < 12; k++) {
                accA = fmaf(s.a1[k],      s.P[OFF_W2 + k * Hd + o],        accA);
                accB = fmaf(s.a1[k + 12], s.P[OFF_W2 + (k + 12) * Hd + o], accB);
            }
            s.dout[o] = ((accA + accB) + s.P[OFF_B2 + o] - s.h[voff + o]) * 0.03125f;
        }
        __syncthreads();

        // backward into hidden: 96 threads, rotated conflict-free
        if (tid < 96) {
            const int j  = ((tid >> 5) << 3) + ((tid & 31) >> 2);
            const int sl = tid & 3;
            float acc = 0.0f;
            #pragma unroll
            for (int k = 0; k < 16; k++) {
                int o = sl + 4 * ((j + k) & 15);
                acc = fmaf(s.P[OFF_W2 + j * Hd + o], s.dout[o], acc);
            }
            acc += __shfl_xor_sync(0xffffffffu, acc, 1);
            acc += __shfl_xor_sync(0xffffffffu, acc, 2);
            if (sl == 0) s.dz1[j] = (s.a1[j] > 0.0f) ? acc : 0.0f;
        }
        __syncthreads();

        // parameter updates (float4 params, PACKED grads/state)
        {
            float4* P4 = (float4*)s.P;
            // w1: quad (i*24 + j .. j+3), j multiple of 4 — incremental index
            int i = i0, j = j0;
            #pragma unroll
            for (int k = 0; k < 3; k++) {
                float hk = s.h[koff + i];
                ulonglong2 dzp = *(const ulonglong2*)&s.dz1[j];
                ull hk2, gL, gH;
                PACKF2(hk2, hk, hk);
                MULF2(gL, hk2, dzp.x);
                MULF2(gH, hk2, dzp.y);
                adam4p(P4, tid + 128 * k, mW1L[k], mW1H[k], vW1L[k], vW1H[k],
                       gL, gH, negC, epsT, cB1, c01, cB2, c001);
                j += 8; i += 21; if (j >= 24) { j -= 24; i += 1; }
            }
            // w2: quad (jj*64 + o .. o+3)
            #pragma unroll
            for (int k = 0; k < 3; k++) {
                int f = tid + 128 * k;
                float av = s.a1[f >> 4];
                ulonglong2 dvp = ((const ulonglong2*)s.dout)[f & 15];
                ull av2, gL, gH;
                PACKF2(av2, av, av);
                MULF2(gL, av2, dvp.x);
                MULF2(gH, av2, dvp.y);
                adam4p(P4, 390 + f, mW2L[k], mW2H[k], vW2L[k], vW2H[k],
                       gL, gH, negC, epsT, cB1, c01, cB2, c001);
            }
            // b1 (threads 0..5), b2 (threads 32..47) in parallel warps
            if (tid < 6) {
                ulonglong2 dzp = ((const ulonglong2*)s.dz1)[tid];
                adam4p(P4, 384 + tid, mBL, mBH, vBL, vBH,
                       dzp.x, dzp.y, negC, epsT, cB1, c01, cB2, c001);
            }
            if (tid >= 32 && tid < 48) {
                ulonglong2 dvp = ((const ulonglong2*)s.dout)[tid - 32];
                adam4p(P4, 774 + (tid - 32), mBL, mBH, vBL, vBH,
                       dvp.x, dvp.y, negC, epsT, cB1, c01, cB2, c001);
            }
        }
        __syncthreads();
    }

    // ---- query through finetuned MLP + output head ----
    {
        const int qoff = (SEQ - 2) * Hd;
        if (tid < 96) {
            const int j  = ((tid >> 5) << 3) + ((tid & 31) >> 2);
            const int sl = tid & 3;
            float acc = 0.0f;
            #pragma unroll
            for (int k = 0; k < 16; k++)
                acc = fmaf(s.h[qoff + sl + 4 * k], s.P[(sl + 4 * k) * INNER + j], acc);
            acc += __shfl_xor_sync(0xffffffffu, acc, 1);
            acc += __shfl_xor_sync(0xffffffffu, acc, 2);
            if (sl == 0) s.a1[j] = fmaxf(acc + s.P[OFF_B1 + j], 0.0f);
        }
        __syncthreads();
        if (tid < 64) {
            const int o = tid;
            float accA = 0.0f, accB = 0.0f;
            #pragma unroll
            for (int k = 0; k < 12; k++) {
                accA = fmaf(s.a1[k],      s.P[OFF_W2 + k * Hd + o],        accA);
                accB = fmaf(s.a1[k + 12], s.P[OFF_W2 + (k + 12) * Hd + o], accB);
            }
            s.dout[o] = (accA + accB) + s.P[OFF_B2 + o];
        }
        __syncthreads();
        if (tid < Vd) {
            float acc = outb[tid];
            #pragma unroll 8
            for (int o = 0; o < Hd; o++)
                acc = fmaf(s.dout[o], outw[o * Vd + tid], acc);
            out[b * Vd + tid] = acc;
        }
    }
}

extern "C" void kernel_launch(void* const* d_in, const int* in_sizes, int n_in,
                              void* d_out, int out_size) {
    const int*   seqs  = (const int*)  d_in[0];
    const float* embed = (const float*)d_in[1];
    const float* ffw1  = (const float*)d_in[2];
    const float* ffb1  = (const float*)d_in[3];
    const float* ffw2  = (const float*)d_in[4];
    const float* ffb2  = (const float*)d_in[5];
    const float* lng   = (const float*)d_in[6];
    const float* lnb   = (const float*)d_in[7];
    const float* scw   = (const float*)d_in[8];
    const float* scb   = (const float*)d_in[9];
    const float* mw1   = (const float*)d_in[10];
    const float* mb1   = (const float*)d_in[11];
    const float* mw2   = (const float*)d_in[12];
    const float* mb2   = (const float*)d_in[13];
    const float* outw  = (const float*)d_in[14];
    const float* outb  = (const float*)d_in[15];
    float* out = (float*)d_out;

    int B = in_sizes[0] / SEQ;
    ttt_kernel<<<B, 128>>>(seqs, embed, ffw1, ffb1, ffw2, ffb2, lng, lnb,
                           scw, scb, mw1, mb1, mw2, mb2, outw, outb, out);
}

// round 13
// speedup vs baseline: 1.1474x; 1.1474x over previous
#include <cuda_runtime.h>

#define Hd 64
#define Vd 64
#define INNER 24
#define SEQ 32
#define CAP 8
#define NPAIR 15
#define LRc 0.05f
#define B1c 0.9f
#define B2c 0.999f
#define EPSc 1e-8f

#define NW1 (Hd*INNER)             // 1536
#define OFF_B1 NW1                 // 1536
#define OFF_W2 (NW1 + INNER)       // 1560
#define OFF_B2 (OFF_W2 + INNER*Hd) // 3096
#define NPARAM (OFF_B2 + Hd)       // 3160

typedef unsigned long long ull;

// Packed fp32x2 ops (sm_103a FFMA2 path — per-lane IEEE fp32, bit-identical)
#define PACKF2(d, lo, hi) asm("mov.b64 %0, {%1, %2};" : "=l"(d) : "f"(lo), "f"(hi))
#define UNPACKF2(lo, hi, s) asm("mov.b64 {%0, %1}, %2;" : "=f"(lo), "=f"(hi) : "l"(s))
#define FMAF2(d, a, b, c) asm("fma.rn.f32x2 %0, %1, %2, %3;" : "=l"(d) : "l"(a), "l"(b), "l"(c))
#define MULF2(d, a, b) asm("mul.rn.f32x2 %0, %1, %2;" : "=l"(d) : "l"(a), "l"(b))

struct __align__(16) SmemLayout {
    float h[SEQ*Hd];               // 2048 floats
    union {
        float scratch[4096];       // encode-only (4 warps x 1024)
        struct {
            float P[NPARAM];       // params  w1[i*24+j] | b1 | w2[j*64+o] | b2
            float a1[INNER];       // 16B-aligned (P is 12640B)
            float dz1[INNER];
            float dout[Hd];
            float scores[NPAIR + 1];
            float esc[CAP];
            int   ord[CAP];
            int   toks[SEQ];       // only live before encode (pre-scratch)
        };
    };
};

__device__ __forceinline__ float wredsum(float x) {
    #pragma unroll
    for (int o = 16; o; o >>= 1) x += __shfl_xor_sync(0xffffffffu, x, o);
    return x;
}

// Exact eps-folded Adam on a quad; m/v state PACKED in registers, params in smem.
__device__ __forceinline__ void adam4p(float4* __restrict__ P4, int f,
                                       ull& mL, ull& mH, ull& vL, ull& vH,
                                       ull gL, ull gH, float negC, float epsT,
                                       ull cB1, ull c01, ull cB2, ull c001) {
    ull t;
    MULF2(t, c01, gL);  FMAF2(mL, cB1, mL, t);
    MULF2(t, c01, gH);  FMAF2(mH, cB1, mH, t);
    MULF2(t, c001, gL); MULF2(t, t, gL); FMAF2(vL, cB2, vL, t);
    MULF2(t, c001, gH); MULF2(t, t, gH); FMAF2(vH, cB2, vH, t);
    float v0, v1, v2, v3, m0, m1, m2, m3;
    UNPACKF2(v0, v1, vL); UNPACKF2(v2, v3, vH);
    UNPACKF2(m0, m1, mL); UNPACKF2(m2, m3, mH);
    float s0 = fmaxf(v0 * __frsqrt_rn(v0), 0.0f);
    float s1 = fmaxf(v1 * __frsqrt_rn(v1), 0.0f);
    float s2_ = fmaxf(v2 * __frsqrt_rn(v2), 0.0f);
    float s3 = fmaxf(v3 * __frsqrt_rn(v3), 0.0f);
    float4 p = P4[f];
    p.x = fmaf(negC, __fdividef(m0, s0 + epsT), p.x);
    p.y = fmaf(negC, __fdividef(m1, s1 + epsT), p.y);
    p.z = fmaf(negC, __fdividef(m2, s2_ + epsT), p.z);
    p.w = fmaf(negC, __fdividef(m3, s3 + epsT), p.w);
    P4[f] = p;
}

__global__ void __launch_bounds__(128, 4) ttt_kernel(
    const int*   __restrict__ seqs,
    const float* __restrict__ embed,
    const float* __restrict__ ffw1, const float* __restrict__ ffb1,
    const float* __restrict__ ffw2, const float* __restrict__ ffb2,
    const float* __restrict__ lng,  const float* __restrict__ lnb,
    const float* __restrict__ scw,  const float* __restrict__ scb,
    const float* __restrict__ mw1,  const float* __restrict__ mb1,
    const float* __restrict__ mw2,  const float* __restrict__ mb2,
    const float* __restrict__ outw, const float* __restrict__ outb,
    float* __restrict__ out)
{
    __shared__ SmemLayout s;
    const int tid  = threadIdx.x;
    const int lane = tid & 31;
    const int w    = tid >> 5;
    const int b    = blockIdx.x;

    // ---- tokens + embeddings (float4) ----
    if (tid < SEQ) s.toks[tid] = seqs[b * SEQ + tid];
    __syncthreads();
    {
        const float4* e4 = (const float4*)embed;
        float4* h4 = (float4*)s.h;
        #pragma unroll
        for (int r = 0; r < 4; r++) {
            int idx = tid + 128 * r;          // 0..511
            int t = idx >> 4, c = idx & 15;
            h4[idx] = e4[s.toks[t] * 16 + c];
        }
    }
    __syncthreads();

    // ---- encode: warp w handles tokens {w, w+4, ..., w+28} ----
    {
        // layer 1 (PACKED f32x2): lane owns cols [4*lane, 4*lane+4)
        const ulonglong2* w1_p = (const ulonglong2*)ffw1;
        ulonglong2 bbp = ((const ulonglong2*)ffb1)[lane];
        ull accL[8], accH[8];
        #pragma unroll
        for (int tk = 0; tk < 8; tk++) { accL[tk] = bbp.x; accH[tk] = bbp.y; }
        #pragma unroll 2
        for (int ib = 0; ib < Hd; ib += 4) {
            ulonglong2 wv0 = w1_p[(ib + 0) * 32 + lane];
            ulonglong2 wv1 = w1_p[(ib + 1) * 32 + lane];
            ulonglong2 wv2 = w1_p[(ib + 2) * 32 + lane];
            ulonglong2 wv3 = w1_p[(ib + 3) * 32 + lane];
            #pragma unroll
            for (int tk = 0; tk < 8; tk++) {
                float4 ev = *(const float4*)&s.h[(w + 4 * tk) * Hd + ib];
                ull e;
                PACKF2(e, ev.x, ev.x);
                FMAF2(accL[tk], e, wv0.x, accL[tk]);
                FMAF2(accH[tk], e, wv0.y, accH[tk]);
                PACKF2(e, ev.y, ev.y);
                FMAF2(accL[tk], e, wv1.x, accL[tk]);
                FMAF2(accH[tk], e, wv1.y, accH[tk]);
                PACKF2(e, ev.z, ev.z);
                FMAF2(accL[tk], e, wv2.x, accL[tk]);
                FMAF2(accH[tk], e, wv2.y, accH[tk]);
                PACKF2(e, ev.w, ev.w);
                FMAF2(accL[tk], e, wv3.x, accL[tk]);
                FMAF2(accH[tk], e, wv3.y, accH[tk]);
            }
        }
        float4* sc4 = (float4*)s.scratch;
        #pragma unroll
        for (int tk = 0; tk < 8; tk++) {
            float a0, a1_, a2_, a3;
            UNPACKF2(a0, a1_, accL[tk]);
            UNPACKF2(a2_, a3, accH[tk]);
            float4 r;
            r.x = fmaxf(a0, 0.0f);
            r.y = fmaxf(a1_, 0.0f);
            r.z = fmaxf(a2_, 0.0f);
            r.w = fmaxf(a3, 0.0f);
            sc4[w * 256 + tk * 32 + lane] = r;
        }
        __syncwarp();

        // layer 2: lane owns cols [2*lane, 2*lane+2); i blocked by 4 (scalar)
        const float2* w2_2 = (const float2*)ffw2;
        float2 fb = ((const float2*)ffb2)[lane];
        float2 a2[8];
        #pragma unroll
        for (int tk = 0; tk < 8; tk++) a2[tk] = fb;
        #pragma unroll 2
        for (int ib = 0; ib < 2 * Hd; ib += 4) {
            float2 wv0 = w2_2[(ib + 0) * 32 + lane];
            float2 wv1 = w2_2[(ib + 1) * 32 + lane];
            float2 wv2 = w2_2[(ib + 2) * 32 + lane];
            float2 wv3 = w2_2[(ib + 3) * 32 + lane];
            #pragma unroll
            for (int tk = 0; tk < 8; tk++) {
                float4 hv = *(const float4*)&s.scratch[w * 1024 + tk * 128 + ib];
                a2[tk].x = fmaf(hv.x, wv0.x, a2[tk].x);
                a2[tk].y = fmaf(hv.x, wv0.y, a2[tk].y);
                a2[tk].x = fmaf(hv.y, wv1.x, a2[tk].x);
                a2[tk].y = fmaf(hv.y, wv1.y, a2[tk].y);
                a2[tk].x = fmaf(hv.z, wv2.x, a2[tk].x);
                a2[tk].y = fmaf(hv.z, wv2.y, a2[tk].y);
                a2[tk].x = fmaf(hv.w, wv3.x, a2[tk].x);
                a2[tk].y = fmaf(hv.w, wv3.y, a2[tk].y);
            }
        }

        // residual + layernorm
        float2 g2  = ((const float2*)lng)[lane];
        float2 be2 = ((const float2*)lnb)[lane];
        float2* h2 = (float2*)s.h;
        #pragma unroll
        for (int tk = 0; tk < 8; tk++) {
            int t = w + 4 * tk;
            float2 x = h2[t * 32 + lane];
            x.x += a2[tk].x; x.y += a2[tk].y;
            float mean = wredsum(x.x + x.y) * (1.0f / 64.0f);
            float d0 = x.x - mean, d1 = x.y - mean;
            float var = wredsum(d0 * d0 + d1 * d1) * (1.0f / 64.0f);
            float rs = rsqrtf(var + 1e-5f);
            float2 r;
            r.x = fmaf(d0 * rs, g2.x, be2.x);
            r.y = fmaf(d1 * rs, g2.y, be2.y);
            h2[t * 32 + lane] = r;
        }
    }
    __syncthreads();

    // ---- scores (scratch dead from here; P/a1/... region live) ----
    for (int p = w; p < NPAIR; p += 4) {
        const float* kk = &s.h[(2 * p)     * Hd];
        const float* vv = &s.h[(2 * p + 1) * Hd];
        float acc = kk[lane]      * scw[lane]
                  + kk[lane + 32] * scw[lane + 32]
                  + vv[lane]      * scw[lane + 64]
                  + vv[lane + 32] * scw[lane + 96];
        acc = wredsum(acc);
        if (lane == 0) s.scores[p] = acc + scb[0];
    }
    __syncthreads();

    // ---- evict-min (thread 0) overlapped with P init (all) ----
    if (tid == 0) {
        #pragma unroll
        for (int i = 0; i < CAP; i++) { s.ord[i] = i; s.esc[i] = s.scores[i]; }
        for (int n = CAP; n < NPAIR; n++) {
            int mi = 0; float mv = s.esc[0];
            #pragma unroll
            for (int i = 1; i < CAP; i++) if (s.esc[i] < mv) { mv = s.esc[i]; mi = i; }
            for (int i = mi; i < CAP - 1; i++) { s.ord[i] = s.ord[i+1]; s.esc[i] = s.esc[i+1]; }
            s.ord[CAP-1] = n; s.esc[CAP-1] = s.scores[n];
        }
    }
    {
        float4* P4 = (float4*)s.P;
        for (int q = tid; q < 384; q += 128) P4[q]       = ((const float4*)mw1)[q];
        for (int q = tid; q < 384; q += 128) P4[390 + q] = ((const float4*)mw2)[q];
        if (tid < 6)  P4[384 + tid] = ((const float4*)mb1)[tid];
        if (tid >= 32 && tid < 48) P4[774 + (tid - 32)] = ((const float4*)mb2)[tid - 32];
    }
    __syncthreads();

    // per-thread constant index seeds for the w1 float4 update loop
    const int q0 = 4 * tid;
    const int j0 = q0 % 24;     // multiple of 4, row never crossed (24 % 4 == 0)
    const int i0 = q0 / 24;

    // packed Adam constants
    ull cB1, c01, cB2, c001;
    PACKF2(cB1, B1c, B1c);
    PACKF2(c01, 0.1f, 0.1f);
    PACKF2(cB2, B2c, B2c);
    PACKF2(c001, 0.001f, 0.001f);

    // ---- Adam state PACKED in registers (same param indices every step) ----
    ull mW1L[3], mW1H[3], vW1L[3], vW1H[3];
    ull mW2L[3], mW2H[3], vW2L[3], vW2H[3];
    ull mBL = 0, mBH = 0, vBL = 0, vBH = 0;
    #pragma unroll
    for (int k = 0; k < 3; k++) {
        mW1L[k] = mW1H[k] = vW1L[k] = vW1H[k] = 0;
        mW2L[k] = mW2H[k] = vW2L[k] = vW2H[k] = 0;
    }

    // ---- 8 inner Adam steps ----
    float pb1 = 1.0f, pb2 = 1.0f;
    #pragma unroll 1
    for (int st = 0; st < CAP; st++) {
        pb1 *= B1c; pb2 *= B2c;
        float inv1 = __fdividef(1.0f, 1.0f - pb1);
        float s2   = sqrtf(1.0f - pb2);
        float negC = -LRc * inv1 * s2;
        float epsT = EPSc * s2;
        int koff = (s.ord[st] << 1) * Hd;
        int voff = koff + Hd;

        // fwd layer1: 96 threads, 4 lanes per j
        if (tid < 96) {
            const int j  = ((tid >> 5) << 3) + ((tid & 31) >> 2);
            const int sl = tid & 3;
            float acc = 0.0f;
            #pragma unroll
            for (int k = 0; k < 16; k++)
                acc = fmaf(s.h[koff + sl + 4 * k], s.P[(sl + 4 * k) * INNER + j], acc);
            acc += __shfl_xor_sync(0xffffffffu, acc, 1);
            acc += __shfl_xor_sync(0xffffffffu, acc, 2);
            if (sl == 0) s.a1[j] = fmaxf(acc + s.P[OFF_B1 + j], 0.0f);
        }
        __syncthreads();

        // fwd layer2 + output grad: 64 threads, 1 lane per o, conflict-free,
        // two chains summed in the same order as the old shfl pair (bit-identical)
        if (tid < 64) {
            const int o = tid;
            float accA = 0.0f, accB = 0.0f;
            #pragma unroll
            for (int k = 0; k < 12; k++) {
                accA = fmaf(s.a1[k],      s.P[OFF_W2 + k * Hd + o],        accA);
                accB = fmaf(s.a1[k + 12], s.P[OFF_W2 + (k + 12) * Hd + o], accB);
            }
            s.dout[o] = ((accA + accB) + s.P[OFF_B2 + o] - s.h[voff + o]) * 0.03125f;
        }
        __syncthreads();

        // backward into hidden: 96 threads, rotated conflict-free
        if (tid < 96) {
            const int j  = ((tid >> 5) << 3) + ((tid & 31) >> 2);
            const int sl = tid & 3;
            float acc = 0.0f;
            #pragma unroll
            for (int k = 0; k < 16; k++) {
                int o = sl + 4 * ((j + k) & 15);
                acc = fmaf(s.P[OFF_W2 + j * Hd + o], s.dout[o], acc);
            }
            acc += __shfl_xor_sync(0xffffffffu, acc, 1);
            acc += __shfl_xor_sync(0xffffffffu, acc, 2);
            if (sl == 0) s.dz1[j] = (s.a1[j] > 0.0f) ? acc : 0.0f;
        }
        __syncthreads();

        // parameter updates (float4 params, PACKED grads/state)
        {
            float4* P4 = (float4*)s.P;
            // w1: quad (i*24 + j .. j+3), j multiple of 4 — incremental index
            int i = i0, j = j0;
            #pragma unroll
            for (int k = 0; k < 3; k++) {
                float hk = s.h[koff + i];
                ulonglong2 dzp = *(const ulonglong2*)&s.dz1[j];
                ull hk2, gL, gH;
                PACKF2(hk2, hk, hk);
                MULF2(gL, hk2, dzp.x);
                MULF2(gH, hk2, dzp.y);
                adam4p(P4, tid + 128 * k, mW1L[k], mW1H[k], vW1L[k], vW1H[k],
                       gL, gH, negC, epsT, cB1, c01, cB2, c001);
                j += 8; i += 21; if (j >= 24) { j -= 24; i += 1; }
            }
            // w2: quad (jj*64 + o .. o+3)
            #pragma unroll
            for (int k = 0; k < 3; k++) {
                int f = tid + 128 * k;
                float av = s.a1[f >> 4];
                ulonglong2 dvp = ((const ulonglong2*)s.dout)[f & 15];
                ull av2, gL, gH;
                PACKF2(av2, av, av);
                MULF2(gL, av2, dvp.x);
                MULF2(gH, av2, dvp.y);
                adam4p(P4, 390 + f, mW2L[k], mW2H[k], vW2L[k], vW2H[k],
                       gL, gH, negC, epsT, cB1, c01, cB2, c001);
            }
            // b1 (threads 0..5), b2 (threads 32..47) in parallel warps
            if (tid < 6) {
                ulonglong2 dzp = ((const ulonglong2*)s.dz1)[tid];
                adam4p(P4, 384 + tid, mBL, mBH, vBL, vBH,
                       dzp.x, dzp.y, negC, epsT, cB1, c01, cB2, c001);
            }
            if (tid >= 32 && tid < 48) {
                ulonglong2 dvp = ((const ulonglong2*)s.dout)[tid - 32];
                adam4p(P4, 774 + (tid - 32), mBL, mBH, vBL, vBH,
                       dvp.x, dvp.y, negC, epsT, cB1, c01, cB2, c001);
            }
        }
        __syncthreads();
    }

    // ---- query through finetuned MLP + output head ----
    {
        const int qoff = (SEQ - 2) * Hd;
        if (tid < 96) {
            const int j  = ((tid >> 5) << 3) + ((tid & 31) >> 2);
            const int sl = tid & 3;
            float acc = 0.0f;
            #pragma unroll
            for (int k = 0; k < 16; k++)
                acc = fmaf(s.h[qoff + sl + 4 * k], s.P[(sl + 4 * k) * INNER + j], acc);
            acc += __shfl_xor_sync(0xffffffffu, acc, 1);
            acc += __shfl_xor_sync(0xffffffffu, acc, 2);
            if (sl == 0) s.a1[j] = fmaxf(acc + s.P[OFF_B1 + j], 0.0f);
        }
        __syncthreads();
        if (tid < 64) {
            const int o = tid;
            float accA = 0.0f, accB = 0.0f;
            #pragma unroll
            for (int k = 0; k < 12; k++) {
                accA = fmaf(s.a1[k],      s.P[OFF_W2 + k * Hd + o],        accA);
                accB = fmaf(s.a1[k + 12], s.P[OFF_W2 + (k + 12) * Hd + o], accB);
            }
            s.dout[o] = (accA + accB) + s.P[OFF_B2 + o];
        }
        __syncthreads();
        if (tid < Vd) {
            float acc = outb[tid];
            #pragma unroll 8
            for (int o = 0; o < Hd; o++)
                acc = fmaf(s.dout[o], outw[o * Vd + tid], acc);
            out[b * Vd + tid] = acc;
        }
    }
}

extern "C" void kernel_launch(void* const* d_in, const int* in_sizes, int n_in,
                              void* d_out, int out_size) {
    const int*   seqs  = (const int*)  d_in[0];
    const float* embed = (const float*)d_in[1];
    const float* ffw1  = (const float*)d_in[2];
    const float* ffb1  = (const float*)d_in[3];
    const float* ffw2  = (const float*)d_in[4];
    const float* ffb2  = (const float*)d_in[5];
    const float* lng   = (const float*)d_in[6];
    const float* lnb   = (const float*)d_in[7];
    const float* scw   = (const float*)d_in[8];
    const float* scb   = (const float*)d_in[9];
    const float* mw1   = (const float*)d_in[10];
    const float* mb1   = (const float*)d_in[11];
    const float* mw2   = (const float*)d_in[12];
    const float* mb2   = (const float*)d_in[13];
    const float* outw  = (const float*)d_in[14];
    const float* outb  = (const float*)d_in[15];
    float* out = (float*)d_out;

    int B = in_sizes[0] / SEQ;
    ttt_kernel<<<B, 128>>>(seqs, embed, ffw1, ffb1, ffw2, ffb2, lng, lnb,
                           scw, scb, mw1, mb1, mw2, mb2, outw, outb, out);
}

// round 14
// speedup vs baseline: 1.1639x; 1.0144x over previous
#include <cuda_runtime.h>

#define Hd 64
#define Vd 64
#define INNER 24
#define SEQ 32
#define CAP 8
#define NPAIR 15
#define LRc 0.05f
#define B1c 0.9f
#define B2c 0.999f
#define EPSc 1e-8f

#define NW1 (Hd*INNER)             // 1536
#define OFF_B1 NW1                 // 1536
#define OFF_W2 (NW1 + INNER)       // 1560
#define OFF_B2 (OFF_W2 + INNER*Hd) // 3096
#define NPARAM (OFF_B2 + Hd)       // 3160

typedef unsigned long long ull;

// Packed fp32x2 ops (sm_103a FFMA2 path — per-lane IEEE fp32, bit-identical)
#define PACKF2(d, lo, hi) asm("mov.b64 %0, {%1, %2};" : "=l"(d) : "f"(lo), "f"(hi))
#define UNPACKF2(lo, hi, s) asm("mov.b64 {%0, %1}, %2;" : "=f"(lo), "=f"(hi) : "l"(s))
#define FMAF2(d, a, b, c) asm("fma.rn.f32x2 %0, %1, %2, %3;" : "=l"(d) : "l"(a), "l"(b), "l"(c))
#define MULF2(d, a, b) asm("mul.rn.f32x2 %0, %1, %2;" : "=l"(d) : "l"(a), "l"(b))

struct __align__(16) SmemLayout {
    float h[SEQ*Hd];               // 2048 floats (8KB)
    union {
        float scratch[4096];       // encode-only (4 warps x 1024, 16KB)
        struct {
            float P[NPARAM];       // params  w1[i*24+j] | b1 | w2[j*64+o] | b2 (12640B)
            float Vv[NPARAM];      // Adam v (smem; m stays in registers)
            float a1[INNER];       // 16B-aligned
            float dz1[INNER];
            float dout[Hd];
            float scores[NPAIR + 1];
            float esc[CAP];
            int   ord[CAP];
            int   toks[SEQ];       // only live before encode (pre-scratch)
        };
    };
};

__device__ __forceinline__ float wredsum(float x) {
    #pragma unroll
    for (int o = 16; o; o >>= 1) x += __shfl_xor_sync(0xffffffffu, x, o);
    return x;
}

// Exact eps-folded Adam on a quad; m PACKED in registers, v in smem, params in smem.
// Per-component op order identical to prior rounds (bit-identical):
//   m = fma(B1, m, 0.1*g);  v = fma(B2, v, (0.001*g)*g)
//   s = max(v*rsqrt(v), 0); p += negC * (m / (s + epsT))
__device__ __forceinline__ void adam4s(float4* __restrict__ P4, float4* __restrict__ V4,
                                       int f, ull& mL, ull& mH,
                                       ull gL, ull gH, float negC, float epsT,
                                       ull cB1, ull c01) {
    ull t;
    MULF2(t, c01, gL);  FMAF2(mL, cB1, mL, t);
    MULF2(t, c01, gH);  FMAF2(mH, cB1, mH, t);
    float g0, g1, g2, g3;
    UNPACKF2(g0, g1, gL); UNPACKF2(g2, g3, gH);
    float4 v = V4[f];
    v.x = fmaf(B2c, v.x, (0.001f * g0) * g0);
    v.y = fmaf(B2c, v.y, (0.001f * g1) * g1);
    v.z = fmaf(B2c, v.z, (0.001f * g2) * g2);
    v.w = fmaf(B2c, v.w, (0.001f * g3) * g3);
    V4[f] = v;
    float m0, m1, m2, m3;
    UNPACKF2(m0, m1, mL); UNPACKF2(m2, m3, mH);
    float s0 = fmaxf(v.x * __frsqrt_rn(v.x), 0.0f);
    float s1 = fmaxf(v.y * __frsqrt_rn(v.y), 0.0f);
    float s2_ = fmaxf(v.z * __frsqrt_rn(v.z), 0.0f);
    float s3 = fmaxf(v.w * __frsqrt_rn(v.w), 0.0f);
    float4 p = P4[f];
    p.x = fmaf(negC, __fdividef(m0, s0 + epsT), p.x);
    p.y = fmaf(negC, __fdividef(m1, s1 + epsT), p.y);
    p.z = fmaf(negC, __fdividef(m2, s2_ + epsT), p.z);
    p.w = fmaf(negC, __fdividef(m3, s3 + epsT), p.w);
    P4[f] = p;
}

__global__ void __launch_bounds__(128, 5) ttt_kernel(
    const int*   __restrict__ seqs,
    const float* __restrict__ embed,
    const float* __restrict__ ffw1, const float* __restrict__ ffb1,
    const float* __restrict__ ffw2, const float* __restrict__ ffb2,
    const float* __restrict__ lng,  const float* __restrict__ lnb,
    const float* __restrict__ scw,  const float* __restrict__ scb,
    const float* __restrict__ mw1,  const float* __restrict__ mb1,
    const float* __restrict__ mw2,  const float* __restrict__ mb2,
    const float* __restrict__ outw, const float* __restrict__ outb,
    float* __restrict__ out)
{
    __shared__ SmemLayout s;
    const int tid  = threadIdx.x;
    const int lane = tid & 31;
    const int w    = tid >> 5;
    const int b    = blockIdx.x;

    // ---- tokens + embeddings (float4) ----
    if (tid < SEQ) s.toks[tid] = seqs[b * SEQ + tid];
    __syncthreads();
    {
        const float4* e4 = (const float4*)embed;
        float4* h4 = (float4*)s.h;
        #pragma unroll
        for (int r = 0; r < 4; r++) {
            int idx = tid + 128 * r;          // 0..511
            int t = idx >> 4, c = idx & 15;
            h4[idx] = e4[s.toks[t] * 16 + c];
        }
    }
    __syncthreads();

    // ---- encode: warp w handles tokens {w, w+4, ..., w+28} ----
    {
        // layer 1 (PACKED f32x2): lane owns cols [4*lane, 4*lane+4)
        const ulonglong2* w1_p = (const ulonglong2*)ffw1;
        ulonglong2 bbp = ((const ulonglong2*)ffb1)[lane];
        ull accL[8], accH[8];
        #pragma unroll
        for (int tk = 0; tk < 8; tk++) { accL[tk] = bbp.x; accH[tk] = bbp.y; }
        #pragma unroll 2
        for (int ib = 0; ib < Hd; ib += 4) {
            ulonglong2 wv0 = w1_p[(ib + 0) * 32 + lane];
            ulonglong2 wv1 = w1_p[(ib + 1) * 32 + lane];
            ulonglong2 wv2 = w1_p[(ib + 2) * 32 + lane];
            ulonglong2 wv3 = w1_p[(ib + 3) * 32 + lane];
            #pragma unroll
            for (int tk = 0; tk < 8; tk++) {
                float4 ev = *(const float4*)&s.h[(w + 4 * tk) * Hd + ib];
                ull e;
                PACKF2(e, ev.x, ev.x);
                FMAF2(accL[tk], e, wv0.x, accL[tk]);
                FMAF2(accH[tk], e, wv0.y, accH[tk]);
                PACKF2(e, ev.y, ev.y);
                FMAF2(accL[tk], e, wv1.x, accL[tk]);
                FMAF2(accH[tk], e, wv1.y, accH[tk]);
                PACKF2(e, ev.z, ev.z);
                FMAF2(accL[tk], e, wv2.x, accL[tk]);
                FMAF2(accH[tk], e, wv2.y, accH[tk]);
                PACKF2(e, ev.w, ev.w);
                FMAF2(accL[tk], e, wv3.x, accL[tk]);
                FMAF2(accH[tk], e, wv3.y, accH[tk]);
            }
        }
        float4* sc4 = (float4*)s.scratch;
        #pragma unroll
        for (int tk = 0; tk < 8; tk++) {
            float a0, a1_, a2_, a3;
            UNPACKF2(a0, a1_, accL[tk]);
            UNPACKF2(a2_, a3, accH[tk]);
            float4 r;
            r.x = fmaxf(a0, 0.0f);
            r.y = fmaxf(a1_, 0.0f);
            r.z = fmaxf(a2_, 0.0f);
            r.w = fmaxf(a3, 0.0f);
            sc4[w * 256 + tk * 32 + lane] = r;
        }
        __syncwarp();

        // layer 2: lane owns cols [2*lane, 2*lane+2); i blocked by 4 (scalar)
        const float2* w2_2 = (const float2*)ffw2;
        float2 fb = ((const float2*)ffb2)[lane];
        float2 a2[8];
        #pragma unroll
        for (int tk = 0; tk < 8; tk++) a2[tk] = fb;
        #pragma unroll 2
        for (int ib = 0; ib < 2 * Hd; ib += 4) {
            float2 wv0 = w2_2[(ib + 0) * 32 + lane];
            float2 wv1 = w2_2[(ib + 1) * 32 + lane];
            float2 wv2 = w2_2[(ib + 2) * 32 + lane];
            float2 wv3 = w2_2[(ib + 3) * 32 + lane];
            #pragma unroll
            for (int tk = 0; tk < 8; tk++) {
                float4 hv = *(const float4*)&s.scratch[w * 1024 + tk * 128 + ib];
                a2[tk].x = fmaf(hv.x, wv0.x, a2[tk].x);
                a2[tk].y = fmaf(hv.x, wv0.y, a2[tk].y);
                a2[tk].x = fmaf(hv.y, wv1.x, a2[tk].x);
                a2[tk].y = fmaf(hv.y, wv1.y, a2[tk].y);
                a2[tk].x = fmaf(hv.z, wv2.x, a2[tk].x);
                a2[tk].y = fmaf(hv.z, wv2.y, a2[tk].y);
                a2[tk].x = fmaf(hv.w, wv3.x, a2[tk].x);
                a2[tk].y = fmaf(hv.w, wv3.y, a2[tk].y);
            }
        }

        // residual + layernorm
        float2 g2  = ((const float2*)lng)[lane];
        float2 be2 = ((const float2*)lnb)[lane];
        float2* h2 = (float2*)s.h;
        #pragma unroll
        for (int tk = 0; tk < 8; tk++) {
            int t = w + 4 * tk;
            float2 x = h2[t * 32 + lane];
            x.x += a2[tk].x; x.y += a2[tk].y;
            float mean = wredsum(x.x + x.y) * (1.0f / 64.0f);
            float d0 = x.x - mean, d1 = x.y - mean;
            float var = wredsum(d0 * d0 + d1 * d1) * (1.0f / 64.0f);
            float rs = rsqrtf(var + 1e-5f);
            float2 r;
            r.x = fmaf(d0 * rs, g2.x, be2.x);
            r.y = fmaf(d1 * rs, g2.y, be2.y);
            h2[t * 32 + lane] = r;
        }
    }
    __syncthreads();

    // ---- scores (scratch dead from here; P/Vv/a1/... region live) ----
    for (int p = w; p < NPAIR; p += 4) {
        const float* kk = &s.h[(2 * p)     * Hd];
        const float* vv = &s.h[(2 * p + 1) * Hd];
        float acc = kk[lane]      * scw[lane]
                  + kk[lane + 32] * scw[lane + 32]
                  + vv[lane]      * scw[lane + 64]
                  + vv[lane + 32] * scw[lane + 96];
        acc = wredsum(acc);
        if (lane == 0) s.scores[p] = acc + scb[0];
    }
    __syncthreads();

    // ---- evict-min (thread 0) overlapped with P init + v zero (all) ----
    if (tid == 0) {
        #pragma unroll
        for (int i = 0; i < CAP; i++) { s.ord[i] = i; s.esc[i] = s.scores[i]; }
        for (int n = CAP; n < NPAIR; n++) {
            int mi = 0; float mv = s.esc[0];
            #pragma unroll
            for (int i = 1; i < CAP; i++) if (s.esc[i] < mv) { mv = s.esc[i]; mi = i; }
            for (int i = mi; i < CAP - 1; i++) { s.ord[i] = s.ord[i+1]; s.esc[i] = s.esc[i+1]; }
            s.ord[CAP-1] = n; s.esc[CAP-1] = s.scores[n];
        }
    }
    {
        float4* P4 = (float4*)s.P;
        float4* V4 = (float4*)s.Vv;
        for (int q = tid; q < 384; q += 128) P4[q]       = ((const float4*)mw1)[q];
        for (int q = tid; q < 384; q += 128) P4[390 + q] = ((const float4*)mw2)[q];
        if (tid < 6)  P4[384 + tid] = ((const float4*)mb1)[tid];
        if (tid >= 32 && tid < 48) P4[774 + (tid - 32)] = ((const float4*)mb2)[tid - 32];
        float4 z4 = make_float4(0.f, 0.f, 0.f, 0.f);
        for (int q = tid; q < 790; q += 128) V4[q] = z4;
    }
    __syncthreads();

    // per-thread constant index seeds for the w1 float4 update loop
    const int q0 = 4 * tid;
    const int j0 = q0 % 24;     // multiple of 4, row never crossed (24 % 4 == 0)
    const int i0 = q0 / 24;

    // packed Adam constants (m-path only)
    ull cB1, c01;
    PACKF2(cB1, B1c, B1c);
    PACKF2(c01, 0.1f, 0.1f);

    // ---- Adam m-state PACKED in registers; v-state in smem ----
    ull mW1L[3], mW1H[3], mW2L[3], mW2H[3];
    ull mBL = 0, mBH = 0;
    #pragma unroll
    for (int k = 0; k < 3; k++) {
        mW1L[k] = mW1H[k] = 0;
        mW2L[k] = mW2H[k] = 0;
    }

    // ---- 8 inner Adam steps ----
    float pb1 = 1.0f, pb2 = 1.0f;
    #pragma unroll 1
    for (int st = 0; st < CAP; st++) {
        pb1 *= B1c; pb2 *= B2c;
        float inv1 = __fdividef(1.0f, 1.0f - pb1);
        float s2   = sqrtf(1.0f - pb2);
        float negC = -LRc * inv1 * s2;
        float epsT = EPSc * s2;
        int koff = (s.ord[st] << 1) * Hd;
        int voff = koff + Hd;

        // fwd layer1: 96 threads, 4 lanes per j
        if (tid < 96) {
            const int j  = ((tid >> 5) << 3) + ((tid & 31) >> 2);
            const int sl = tid & 3;
            float acc = 0.0f;
            #pragma unroll
            for (int k = 0; k < 16; k++)
                acc = fmaf(s.h[koff + sl + 4 * k], s.P[(sl + 4 * k) * INNER + j], acc);
            acc += __shfl_xor_sync(0xffffffffu, acc, 1);
            acc += __shfl_xor_sync(0xffffffffu, acc, 2);
            if (sl == 0) s.a1[j] = fmaxf(acc + s.P[OFF_B1 + j], 0.0f);
        }
        __syncthreads();

        // fwd layer2 + output grad: 64 threads, 1 lane per o, conflict-free
        if (tid < 64) {
            const int o = tid;
            float accA = 0.0f, accB = 0.0f;
            #pragma unroll
            for (int k = 0; k < 12; k++) {
                accA = fmaf(s.a1[k],      s.P[OFF_W2 + k * Hd + o],        accA);
                accB = fmaf(s.a1[k + 12], s.P[OFF_W2 + (k + 12) * Hd + o], accB);
            }
            s.dout[o] = ((accA + accB) + s.P[OFF_B2 + o] - s.h[voff + o]) * 0.03125f;
        }
        __syncthreads();

        // backward into hidden: 96 threads, rotated conflict-free
        if (tid < 96) {
            const int j  = ((tid >> 5) << 3) + ((tid & 31) >> 2);
            const int sl = tid & 3;
            float acc = 0.0f;
            #pragma unroll
            for (int k = 0; k < 16; k++) {
                int o = sl + 4 * ((j + k) & 15);
                acc = fmaf(s.P[OFF_W2 + j * Hd + o], s.dout[o], acc);
            }
            acc += __shfl_xor_sync(0xffffffffu, acc, 1);
            acc += __shfl_xor_sync(0xffffffffu, acc, 2);
            if (sl == 0) s.dz1[j] = (s.a1[j] > 0.0f) ? acc : 0.0f;
        }
        __syncthreads();

        // parameter updates (float4 params, packed m in regs, v in smem)
        {
            float4* P4 = (float4*)s.P;
            float4* V4 = (float4*)s.Vv;
            // w1: quad (i*24 + j .. j+3), j multiple of 4 — incremental index
            int i = i0, j = j0;
            #pragma unroll
            for (int k = 0; k < 3; k++) {
                float hk = s.h[koff + i];
                ulonglong2 dzp = *(const ulonglong2*)&s.dz1[j];
                ull hk2, gL, gH;
                PACKF2(hk2, hk, hk);
                MULF2(gL, hk2, dzp.x);
                MULF2(gH, hk2, dzp.y);
                adam4s(P4, V4, tid + 128 * k, mW1L[k], mW1H[k],
                       gL, gH, negC, epsT, cB1, c01);
                j += 8; i += 21; if (j >= 24) { j -= 24; i += 1; }
            }
            // w2: quad (jj*64 + o .. o+3)
            #pragma unroll
            for (int k = 0; k < 3; k++) {
                int f = tid + 128 * k;
                float av = s.a1[f >> 4];
                ulonglong2 dvp = ((const ulonglong2*)s.dout)[f & 15];
                ull av2, gL, gH;
                PACKF2(av2, av, av);
                MULF2(gL, av2, dvp.x);
                MULF2(gH, av2, dvp.y);
                adam4s(P4, V4, 390 + f, mW2L[k], mW2H[k],
                       gL, gH, negC, epsT, cB1, c01);
            }
            // b1 (threads 0..5), b2 (threads 32..47) in parallel warps
            if (tid < 6) {
                ulonglong2 dzp = ((const ulonglong2*)s.dz1)[tid];
                adam4s(P4, V4, 384 + tid, mBL, mBH,
                       dzp.x, dzp.y, negC, epsT, cB1, c01);
            }
            if (tid >= 32 && tid < 48) {
                ulonglong2 dvp = ((const ulonglong2*)s.dout)[tid - 32];
                adam4s(P4, V4, 774 + (tid - 32), mBL, mBH,
                       dvp.x, dvp.y, negC, epsT, cB1, c01);
            }
        }
        __syncthreads();
    }

    // ---- query through finetuned MLP + output head ----
    {
        const int qoff = (SEQ - 2) * Hd;
        if (tid < 96) {
            const int j  = ((tid >> 5) << 3) + ((tid & 31) >> 2);
            const int sl = tid & 3;
            float acc = 0.0f;
            #pragma unroll
            for (int k = 0; k < 16; k++)
                acc = fmaf(s.h[qoff + sl + 4 * k], s.P[(sl + 4 * k) * INNER + j], acc);
            acc += __shfl_xor_sync(0xffffffffu, acc, 1);
            acc += __shfl_xor_sync(0xffffffffu, acc, 2);
            if (sl == 0) s.a1[j] = fmaxf(acc + s.P[OFF_B1 + j], 0.0f);
        }
        __syncthreads();
        if (tid < 64) {
            const int o = tid;
            float accA = 0.0f, accB = 0.0f;
            #pragma unroll
            for (int k = 0; k < 12; k++) {
                accA = fmaf(s.a1[k],      s.P[OFF_W2 + k * Hd + o],        accA);
                accB = fmaf(s.a1[k + 12], s.P[OFF_W2 + (k + 12) * Hd + o], accB);
            }
            s.dout[o] = (accA + accB) + s.P[OFF_B2 + o];
        }
        __syncthreads();
        if (tid < Vd) {
            float acc = outb[tid];
            #pragma unroll 8
            for (int o = 0; o < Hd; o++)
                acc = fmaf(s.dout[o], outw[o * Vd + tid], acc);
            out[b * Vd + tid] = acc;
        }
    }
}

extern "C" void kernel_launch(void* const* d_in, const int* in_sizes, int n_in,
                              void* d_out, int out_size) {
    const int*   seqs  = (const int*)  d_in[0];
    const float* embed = (const float*)d_in[1];
    const float* ffw1  = (const float*)d_in[2];
    const float* ffb1  = (const float*)d_in[3];
    const float* ffw2  = (const float*)d_in[4];
    const float* ffb2  = (const float*)d_in[5];
    const float* lng   = (const float*)d_in[6];
    const float* lnb   = (const float*)d_in[7];
    const float* scw   = (const float*)d_in[8];
    const float* scb   = (const float*)d_in[9];
    const float* mw1   = (const float*)d_in[10];
    const float* mb1   = (const float*)d_in[11];
    const float* mw2   = (const float*)d_in[12];
    const float* mb2   = (const float*)d_in[13];
    const float* outw  = (const float*)d_in[14];
    const float* outb  = (const float*)d_in[15];
    float* out = (float*)d_out;

    int B = in_sizes[0] / SEQ;
    ttt_kernel<<<B, 128>>>(seqs, embed, ffw1, ffb1, ffw2, ffb2, lng, lnb,
                           scw, scb, mw1, mb1, mw2, mb2, outw, outb, out);
}

// round 15
// speedup vs baseline: 1.2070x; 1.0371x over previous
#include <cuda_runtime.h>

#define Hd 64
#define Vd 64
#define INNER 24
#define SEQ 32
#define CAP 8
#define NPAIR 15
#define LRc 0.05f
#define B1c 0.9f
#define B2c 0.999f
#define EPSc 1e-8f

#define NW1 (Hd*INNER)             // 1536
#define OFF_B1 NW1                 // 1536
#define OFF_W2 (NW1 + INNER)       // 1560
#define OFF_B2 (OFF_W2 + INNER*Hd) // 3096
#define NPARAM (OFF_B2 + Hd)       // 3160

typedef unsigned long long ull;

// Packed fp32x2 ops (sm_103a FFMA2 path — per-lane IEEE fp32, bit-identical)
#define PACKF2(d, lo, hi) asm("mov.b64 %0, {%1, %2};" : "=l"(d) : "f"(lo), "f"(hi))
#define UNPACKF2(lo, hi, s) asm("mov.b64 {%0, %1}, %2;" : "=f"(lo), "=f"(hi) : "l"(s))
#define FMAF2(d, a, b, c) asm("fma.rn.f32x2 %0, %1, %2, %3;" : "=l"(d) : "l"(a), "l"(b), "l"(c))
#define MULF2(d, a, b) asm("mul.rn.f32x2 %0, %1, %2;" : "=l"(d) : "l"(a), "l"(b))

struct __align__(16) SmemLayout {
    float h[SEQ*Hd];               // 2048 floats (8KB)
    union {
        float scratch[4096];       // encode-only (4 warps x 1024, 16KB)
        struct {
            float P[NPARAM];       // params  w1[i*24+j] | b1 | w2[j*64+o] | b2 (12640B)
            float Vv[NPARAM];      // Adam v (smem; m stays in registers)
            float a1[INNER];       // 16B-aligned
            float dz1[INNER];
            float dout[Hd];
            float scores[NPAIR + 1];
            float esc[CAP];
            int   ord[CAP];
            int   toks[SEQ];       // only live before encode (pre-scratch)
        };
    };
};

__device__ __forceinline__ float wredsum(float x) {
    #pragma unroll
    for (int o = 16; o; o >>= 1) x += __shfl_xor_sync(0xffffffffu, x, o);
    return x;
}

// Exact eps-folded Adam on a quad; m PACKED in registers, v in smem, params in smem.
// Per-component op order identical to prior rounds (bit-identical):
//   m = fma(B1, m, 0.1*g);  v = fma(B2, v, (0.001*g)*g)
//   s = max(v*rsqrt(v), 0); p += negC * (m / (s + epsT))
__device__ __forceinline__ void adam4s(float4* __restrict__ P4, float4* __restrict__ V4,
                                       int f, ull& mL, ull& mH,
                                       ull gL, ull gH, float negC, float epsT,
                                       ull cB1, ull c01) {
    ull t;
    MULF2(t, c01, gL);  FMAF2(mL, cB1, mL, t);
    MULF2(t, c01, gH);  FMAF2(mH, cB1, mH, t);
    float g0, g1, g2, g3;
    UNPACKF2(g0, g1, gL); UNPACKF2(g2, g3, gH);
    float4 v = V4[f];
    v.x = fmaf(B2c, v.x, (0.001f * g0) * g0);
    v.y = fmaf(B2c, v.y, (0.001f * g1) * g1);
    v.z = fmaf(B2c, v.z, (0.001f * g2) * g2);
    v.w = fmaf(B2c, v.w, (0.001f * g3) * g3);
    V4[f] = v;
    float m0, m1, m2, m3;
    UNPACKF2(m0, m1, mL); UNPACKF2(m2, m3, mH);
    float s0 = fmaxf(v.x * __frsqrt_rn(v.x), 0.0f);
    float s1 = fmaxf(v.y * __frsqrt_rn(v.y), 0.0f);
    float s2_ = fmaxf(v.z * __frsqrt_rn(v.z), 0.0f);
    float s3 = fmaxf(v.w * __frsqrt_rn(v.w), 0.0f);
    float4 p = P4[f];
    p.x = fmaf(negC, __fdividef(m0, s0 + epsT), p.x);
    p.y = fmaf(negC, __fdividef(m1, s1 + epsT), p.y);
    p.z = fmaf(negC, __fdividef(m2, s2_ + epsT), p.z);
    p.w = fmaf(negC, __fdividef(m3, s3 + epsT), p.w);
    P4[f] = p;
}

__global__ void __launch_bounds__(128, 6) ttt_kernel(
    const int*   __restrict__ seqs,
    const float* __restrict__ embed,
    const float* __restrict__ ffw1, const float* __restrict__ ffb1,
    const float* __restrict__ ffw2, const float* __restrict__ ffb2,
    const float* __restrict__ lng,  const float* __restrict__ lnb,
    const float* __restrict__ scw,  const float* __restrict__ scb,
    const float* __restrict__ mw1,  const float* __restrict__ mb1,
    const float* __restrict__ mw2,  const float* __restrict__ mb2,
    const float* __restrict__ outw, const float* __restrict__ outb,
    float* __restrict__ out)
{
    __shared__ SmemLayout s;
    const int tid  = threadIdx.x;
    const int lane = tid & 31;
    const int w    = tid >> 5;
    const int b    = blockIdx.x;

    // ---- tokens + embeddings (float4) ----
    if (tid < SEQ) s.toks[tid] = seqs[b * SEQ + tid];
    __syncthreads();
    {
        const float4* e4 = (const float4*)embed;
        float4* h4 = (float4*)s.h;
        #pragma unroll
        for (int r = 0; r < 4; r++) {
            int idx = tid + 128 * r;          // 0..511
            int t = idx >> 4, c = idx & 15;
            h4[idx] = e4[s.toks[t] * 16 + c];
        }
    }
    __syncthreads();

    // ---- encode: warp w handles tokens {w, w+4, ..., w+28} ----
    {
        // layer 1 (PACKED f32x2): lane owns cols [4*lane, 4*lane+4)
        const ulonglong2* w1_p = (const ulonglong2*)ffw1;
        ulonglong2 bbp = ((const ulonglong2*)ffb1)[lane];
        ull accL[8], accH[8];
        #pragma unroll
        for (int tk = 0; tk < 8; tk++) { accL[tk] = bbp.x; accH[tk] = bbp.y; }
        #pragma unroll 2
        for (int ib = 0; ib < Hd; ib += 4) {
            ulonglong2 wv0 = w1_p[(ib + 0) * 32 + lane];
            ulonglong2 wv1 = w1_p[(ib + 1) * 32 + lane];
            ulonglong2 wv2 = w1_p[(ib + 2) * 32 + lane];
            ulonglong2 wv3 = w1_p[(ib + 3) * 32 + lane];
            #pragma unroll
            for (int tk = 0; tk < 8; tk++) {
                float4 ev = *(const float4*)&s.h[(w + 4 * tk) * Hd + ib];
                ull e;
                PACKF2(e, ev.x, ev.x);
                FMAF2(accL[tk], e, wv0.x, accL[tk]);
                FMAF2(accH[tk], e, wv0.y, accH[tk]);
                PACKF2(e, ev.y, ev.y);
                FMAF2(accL[tk], e, wv1.x, accL[tk]);
                FMAF2(accH[tk], e, wv1.y, accH[tk]);
                PACKF2(e, ev.z, ev.z);
                FMAF2(accL[tk], e, wv2.x, accL[tk]);
                FMAF2(accH[tk], e, wv2.y, accH[tk]);
                PACKF2(e, ev.w, ev.w);
                FMAF2(accL[tk], e, wv3.x, accL[tk]);
                FMAF2(accH[tk], e, wv3.y, accH[tk]);
            }
        }
        float4* sc4 = (float4*)s.scratch;
        #pragma unroll
        for (int tk = 0; tk < 8; tk++) {
            float a0, a1_, a2_, a3;
            UNPACKF2(a0, a1_, accL[tk]);
            UNPACKF2(a2_, a3, accH[tk]);
            float4 r;
            r.x = fmaxf(a0, 0.0f);
            r.y = fmaxf(a1_, 0.0f);
            r.z = fmaxf(a2_, 0.0f);
            r.w = fmaxf(a3, 0.0f);
            sc4[w * 256 + tk * 32 + lane] = r;
        }
        __syncwarp();

        // layer 2: lane owns cols [2*lane, 2*lane+2); i blocked by 4 (scalar)
        const float2* w2_2 = (const float2*)ffw2;
        float2 fb = ((const float2*)ffb2)[lane];
        float2 a2[8];
        #pragma unroll
        for (int tk = 0; tk < 8; tk++) a2[tk] = fb;
        #pragma unroll 2
        for (int ib = 0; ib < 2 * Hd; ib += 4) {
            float2 wv0 = w2_2[(ib + 0) * 32 + lane];
            float2 wv1 = w2_2[(ib + 1) * 32 + lane];
            float2 wv2 = w2_2[(ib + 2) * 32 + lane];
            float2 wv3 = w2_2[(ib + 3) * 32 + lane];
            #pragma unroll
            for (int tk = 0; tk < 8; tk++) {
                float4 hv = *(const float4*)&s.scratch[w * 1024 + tk * 128 + ib];
                a2[tk].x = fmaf(hv.x, wv0.x, a2[tk].x);
                a2[tk].y = fmaf(hv.x, wv0.y, a2[tk].y);
                a2[tk].x = fmaf(hv.y, wv1.x, a2[tk].x);
                a2[tk].y = fmaf(hv.y, wv1.y, a2[tk].y);
                a2[tk].x = fmaf(hv.z, wv2.x, a2[tk].x);
                a2[tk].y = fmaf(hv.z, wv2.y, a2[tk].y);
                a2[tk].x = fmaf(hv.w, wv3.x, a2[tk].x);
                a2[tk].y = fmaf(hv.w, wv3.y, a2[tk].y);
            }
        }

        // residual + layernorm
        float2 g2  = ((const float2*)lng)[lane];
        float2 be2 = ((const float2*)lnb)[lane];
        float2* h2 = (float2*)s.h;
        #pragma unroll
        for (int tk = 0; tk < 8; tk++) {
            int t = w + 4 * tk;
            float2 x = h2[t * 32 + lane];
            x.x += a2[tk].x; x.y += a2[tk].y;
            float mean = wredsum(x.x + x.y) * (1.0f / 64.0f);
            float d0 = x.x - mean, d1 = x.y - mean;
            float var = wredsum(d0 * d0 + d1 * d1) * (1.0f / 64.0f);
            float rs = rsqrtf(var + 1e-5f);
            float2 r;
            r.x = fmaf(d0 * rs, g2.x, be2.x);
            r.y = fmaf(d1 * rs, g2.y, be2.y);
            h2[t * 32 + lane] = r;
        }
    }
    __syncthreads();

    // ---- scores (scratch dead from here; P/Vv/a1/... region live) ----
    for (int p = w; p < NPAIR; p += 4) {
        const float* kk = &s.h[(2 * p)     * Hd];
        const float* vv = &s.h[(2 * p + 1) * Hd];
        float acc = kk[lane]      * scw[lane]
                  + kk[lane + 32] * scw[lane + 32]
                  + vv[lane]      * scw[lane + 64]
                  + vv[lane + 32] * scw[lane + 96];
        acc = wredsum(acc);
        if (lane == 0) s.scores[p] = acc + scb[0];
    }
    __syncthreads();

    // ---- evict-min (thread 0) overlapped with P init + v zero (all) ----
    if (tid == 0) {
        #pragma unroll
        for (int i = 0; i < CAP; i++) { s.ord[i] = i; s.esc[i] = s.scores[i]; }
        for (int n = CAP; n < NPAIR; n++) {
            int mi = 0; float mv = s.esc[0];
            #pragma unroll
            for (int i = 1; i < CAP; i++) if (s.esc[i] < mv) { mv = s.esc[i]; mi = i; }
            for (int i = mi; i < CAP - 1; i++) { s.ord[i] = s.ord[i+1]; s.esc[i] = s.esc[i+1]; }
            s.ord[CAP-1] = n; s.esc[CAP-1] = s.scores[n];
        }
    }
    {
        float4* P4 = (float4*)s.P;
        float4* V4 = (float4*)s.Vv;
        for (int q = tid; q < 384; q += 128) P4[q]       = ((const float4*)mw1)[q];
        for (int q = tid; q < 384; q += 128) P4[390 + q] = ((const float4*)mw2)[q];
        if (tid < 6)  P4[384 + tid] = ((const float4*)mb1)[tid];
        if (tid >= 32 && tid < 48) P4[774 + (tid - 32)] = ((const float4*)mb2)[tid - 32];
        float4 z4 = make_float4(0.f, 0.f, 0.f, 0.f);
        for (int q = tid; q < 790; q += 128) V4[q] = z4;
    }
    __syncthreads();

    // per-thread constant index seeds for the w1 float4 update loop
    const int q0 = 4 * tid;
    const int j0 = q0 % 24;     // multiple of 4, row never crossed (24 % 4 == 0)
    const int i0 = q0 / 24;

    // packed Adam constants (m-path only)
    ull cB1, c01;
    PACKF2(cB1, B1c, B1c);
    PACKF2(c01, 0.1f, 0.1f);

    // ---- Adam m-state PACKED in registers; v-state in smem ----
    ull mW1L[3], mW1H[3], mW2L[3], mW2H[3];
    ull mBL = 0, mBH = 0;
    #pragma unroll
    for (int k = 0; k < 3; k++) {
        mW1L[k] = mW1H[k] = 0;
        mW2L[k] = mW2H[k] = 0;
    }

    // ---- 8 inner Adam steps ----
    float pb1 = 1.0f, pb2 = 1.0f;
    #pragma unroll 1
    for (int st = 0; st < CAP; st++) {
        pb1 *= B1c; pb2 *= B2c;
        float inv1 = __fdividef(1.0f, 1.0f - pb1);
        float s2   = sqrtf(1.0f - pb2);
        float negC = -LRc * inv1 * s2;
        float epsT = EPSc * s2;
        int koff = (s.ord[st] << 1) * Hd;
        int voff = koff + Hd;

        // fwd layer1: 96 threads, 4 lanes per j
        if (tid < 96) {
            const int j  = ((tid >> 5) << 3) + ((tid & 31) >> 2);
            const int sl = tid & 3;
            float acc = 0.0f;
            #pragma unroll
            for (int k = 0; k < 16; k++)
                acc = fmaf(s.h[koff + sl + 4 * k], s.P[(sl + 4 * k) * INNER + j], acc);
            acc += __shfl_xor_sync(0xffffffffu, acc, 1);
            acc += __shfl_xor_sync(0xffffffffu, acc, 2);
            if (sl == 0) s.a1[j] = fmaxf(acc + s.P[OFF_B1 + j], 0.0f);
        }
        __syncthreads();

        // fwd layer2 + output grad: 64 threads, 1 lane per o, conflict-free
        if (tid < 64) {
            const int o = tid;
            float accA = 0.0f, accB = 0.0f;
            #pragma unroll
            for (int k = 0; k < 12; k++) {
                accA = fmaf(s.a1[k],      s.P[OFF_W2 + k * Hd + o],        accA);
                accB = fmaf(s.a1[k + 12], s.P[OFF_W2 + (k + 12) * Hd + o], accB);
            }
            s.dout[o] = ((accA + accB) + s.P[OFF_B2 + o] - s.h[voff + o]) * 0.03125f;
        }
        __syncthreads();

        // backward into hidden: 96 threads, rotated conflict-free
        if (tid < 96) {
            const int j  = ((tid >> 5) << 3) + ((tid & 31) >> 2);
            const int sl = tid & 3;
            float acc = 0.0f;
            #pragma unroll
            for (int k = 0; k < 16; k++) {
                int o = sl + 4 * ((j + k) & 15);
                acc = fmaf(s.P[OFF_W2 + j * Hd + o], s.dout[o], acc);
            }
            acc += __shfl_xor_sync(0xffffffffu, acc, 1);
            acc += __shfl_xor_sync(0xffffffffu, acc, 2);
            if (sl == 0) s.dz1[j] = (s.a1[j] > 0.0f) ? acc : 0.0f;
        }
        __syncthreads();

        // parameter updates (float4 params, packed m in regs, v in smem)
        {
            float4* P4 = (float4*)s.P;
            float4* V4 = (float4*)s.Vv;
            // w1: quad (i*24 + j .. j+3), j multiple of 4 — incremental index
            int i = i0, j = j0;
            #pragma unroll
            for (int k = 0; k < 3; k++) {
                float hk = s.h[koff + i];
                ulonglong2 dzp = *(const ulonglong2*)&s.dz1[j];
                ull hk2, gL, gH;
                PACKF2(hk2, hk, hk);
                MULF2(gL, hk2, dzp.x);
                MULF2(gH, hk2, dzp.y);
                adam4s(P4, V4, tid + 128 * k, mW1L[k], mW1H[k],
                       gL, gH, negC, epsT, cB1, c01);
                j += 8; i += 21; if (j >= 24) { j -= 24; i += 1; }
            }
            // w2: quad (jj*64 + o .. o+3)
            #pragma unroll
            for (int k = 0; k < 3; k++) {
                int f = tid + 128 * k;
                float av = s.a1[f >> 4];
                ulonglong2 dvp = ((const ulonglong2*)s.dout)[f & 15];
                ull av2, gL, gH;
                PACKF2(av2, av, av);
                MULF2(gL, av2, dvp.x);
                MULF2(gH, av2, dvp.y);
                adam4s(P4, V4, 390 + f, mW2L[k], mW2H[k],
                       gL, gH, negC, epsT, cB1, c01);
            }
            // b1 (threads 0..5), b2 (threads 32..47) in parallel warps
            if (tid < 6) {
                ulonglong2 dzp = ((const ulonglong2*)s.dz1)[tid];
                adam4s(P4, V4, 384 + tid, mBL, mBH,
                       dzp.x, dzp.y, negC, epsT, cB1, c01);
            }
            if (tid >= 32 && tid < 48) {
                ulonglong2 dvp = ((const ulonglong2*)s.dout)[tid - 32];
                adam4s(P4, V4, 774 + (tid - 32), mBL, mBH,
                       dvp.x, dvp.y, negC, epsT, cB1, c01);
            }
        }
        __syncthreads();
    }

    // ---- query through finetuned MLP + output head ----
    {
        const int qoff = (SEQ - 2) * Hd;
        if (tid < 96) {
            const int j  = ((tid >> 5) << 3) + ((tid & 31) >> 2);
            const int sl = tid & 3;
            float acc = 0.0f;
            #pragma unroll
            for (int k = 0; k < 16; k++)
                acc = fmaf(s.h[qoff + sl + 4 * k], s.P[(sl + 4 * k) * INNER + j], acc);
            acc += __shfl_xor_sync(0xffffffffu, acc, 1);
            acc += __shfl_xor_sync(0xffffffffu, acc, 2);
            if (sl == 0) s.a1[j] = fmaxf(acc + s.P[OFF_B1 + j], 0.0f);
        }
        __syncthreads();
        if (tid < 64) {
            const int o = tid;
            float accA = 0.0f, accB = 0.0f;
            #pragma unroll
            for (int k = 0; k < 12; k++) {
                accA = fmaf(s.a1[k],      s.P[OFF_W2 + k * Hd + o],        accA);
                accB = fmaf(s.a1[k + 12], s.P[OFF_W2 + (k + 12) * Hd + o], accB);
            }
            s.dout[o] = (accA + accB) + s.P[OFF_B2 + o];
        }
        __syncthreads();
        if (tid < Vd) {
            float acc = outb[tid];
            #pragma unroll 8
            for (int o = 0; o < Hd; o++)
                acc = fmaf(s.dout[o], outw[o * Vd + tid], acc);
            out[b * Vd + tid] = acc;
        }
    }
}

extern "C" void kernel_launch(void* const* d_in, const int* in_sizes, int n_in,
                              void* d_out, int out_size) {
    const int*   seqs  = (const int*)  d_in[0];
    const float* embed = (const float*)d_in[1];
    const float* ffw1  = (const float*)d_in[2];
    const float* ffb1  = (const float*)d_in[3];
    const float* ffw2  = (const float*)d_in[4];
    const float* ffb2  = (const float*)d_in[5];
    const float* lng   = (const float*)d_in[6];
    const float* lnb   = (const float*)d_in[7];
    const float* scw   = (const float*)d_in[8];
    const float* scb   = (const float*)d_in[9];
    const float* mw1   = (const float*)d_in[10];
    const float* mb1   = (const float*)d_in[11];
    const float* mw2   = (const float*)d_in[12];
    const float* mb2   = (const float*)d_in[13];
    const float* outw  = (const float*)d_in[14];
    const float* outb  = (const float*)d_in[15];
    float* out = (float*)d_out;

    int B = in_sizes[0] / SEQ;
    ttt_kernel<<<B, 128>>>(seqs, embed, ffw1, ffb1, ffw2, ffb2, lng, lnb,
                           scw, scb, mw1, mb1, mw2, mb2, outw, outb, out);
}

// round 16
// speedup vs baseline: 1.2551x; 1.0399x over previous
#include <cuda_runtime.h>

#define Hd 64
#define Vd 64
#define INNER 24
#define SEQ 32
#define CAP 8
#define NPAIR 15
#define LRc 0.05f
#define B1c 0.9f
#define B2c 0.999f
#define EPSc 1e-8f

#define NW1 (Hd*INNER)             // 1536
#define OFF_B1 NW1                 // 1536
#define OFF_W2 (NW1 + INNER)       // 1560
#define OFF_B2 (OFF_W2 + INNER*Hd) // 3096
#define NPARAM (OFF_B2 + Hd)       // 3160

typedef unsigned long long ull;

// Packed fp32x2 ops (sm_103a FFMA2 path — per-lane IEEE fp32, bit-identical)
#define PACKF2(d, lo, hi) asm("mov.b64 %0, {%1, %2};" : "=l"(d) : "f"(lo), "f"(hi))
#define UNPACKF2(lo, hi, s) asm("mov.b64 {%0, %1}, %2;" : "=f"(lo), "=f"(hi) : "l"(s))
#define FMAF2(d, a, b, c) asm("fma.rn.f32x2 %0, %1, %2, %3;" : "=l"(d) : "l"(a), "l"(b), "l"(c))
#define MULF2(d, a, b) asm("mul.rn.f32x2 %0, %1, %2;" : "=l"(d) : "l"(a), "l"(b))

struct __align__(16) SmemLayout {
    float h[SEQ*Hd];               // 2048 floats (8KB)
    union {
        float scratch[4096];       // encode-only (4 warps x 1024, 16KB)
        struct {
            float P[NPARAM];       // params  w1[i*24+j] | b1 | w2[j*64+o] | b2 (12640B)
            float Vv[NPARAM];      // Adam v (smem; m stays in registers)
            float a1[INNER];       // 16B-aligned
            float dz1[INNER];
            float dout[Hd];
            float scores[NPAIR + 1];
            float esc[CAP];
            int   ord[CAP];
            int   toks[SEQ];       // only live before encode (pre-scratch)
        };
    };
};

__device__ __forceinline__ float wredsum(float x) {
    #pragma unroll
    for (int o = 16; o; o >>= 1) x += __shfl_xor_sync(0xffffffffu, x, o);
    return x;
}

// Exact eps-folded Adam on a quad; m PACKED in registers, v in smem, params in smem.
// Per-component op order identical to prior rounds (bit-identical):
//   m = fma(B1, m, 0.1*g);  v = fma(B2, v, (0.001*g)*g)
//   s = max(v*rsqrt(v), 0); p += negC * (m / (s + epsT))
__device__ __forceinline__ void adam4s(float4* __restrict__ P4, float4* __restrict__ V4,
                                       int f, ull& mL, ull& mH,
                                       ull gL, ull gH, float negC, float epsT,
                                       ull cB1, ull c01) {
    ull t;
    MULF2(t, c01, gL);  FMAF2(mL, cB1, mL, t);
    MULF2(t, c01, gH);  FMAF2(mH, cB1, mH, t);
    float g0, g1, g2, g3;
    UNPACKF2(g0, g1, gL); UNPACKF2(g2, g3, gH);
    float4 v = V4[f];
    v.x = fmaf(B2c, v.x, (0.001f * g0) * g0);
    v.y = fmaf(B2c, v.y, (0.001f * g1) * g1);
    v.z = fmaf(B2c, v.z, (0.001f * g2) * g2);
    v.w = fmaf(B2c, v.w, (0.001f * g3) * g3);
    V4[f] = v;
    float m0, m1, m2, m3;
    UNPACKF2(m0, m1, mL); UNPACKF2(m2, m3, mH);
    float s0 = fmaxf(v.x * __frsqrt_rn(v.x), 0.0f);
    float s1 = fmaxf(v.y * __frsqrt_rn(v.y), 0.0f);
    float s2_ = fmaxf(v.z * __frsqrt_rn(v.z), 0.0f);
    float s3 = fmaxf(v.w * __frsqrt_rn(v.w), 0.0f);
    float4 p = P4[f];
    p.x = fmaf(negC, __fdividef(m0, s0 + epsT), p.x);
    p.y = fmaf(negC, __fdividef(m1, s1 + epsT), p.y);
    p.z = fmaf(negC, __fdividef(m2, s2_ + epsT), p.z);
    p.w = fmaf(negC, __fdividef(m3, s3 + epsT), p.w);
    P4[f] = p;
}

__global__ void __launch_bounds__(128, 6) ttt_kernel(
    const int*   __restrict__ seqs,
    const float* __restrict__ embed,
    const float* __restrict__ ffw1, const float* __restrict__ ffb1,
    const float* __restrict__ ffw2, const float* __restrict__ ffb2,
    const float* __restrict__ lng,  const float* __restrict__ lnb,
    const float* __restrict__ scw,  const float* __restrict__ scb,
    const float* __restrict__ mw1,  const float* __restrict__ mb1,
    const float* __restrict__ mw2,  const float* __restrict__ mb2,
    const float* __restrict__ outw, const float* __restrict__ outb,
    float* __restrict__ out)
{
    __shared__ SmemLayout s;
    const int tid  = threadIdx.x;
    const int lane = tid & 31;
    const int w    = tid >> 5;
    const int b    = blockIdx.x;

    // ---- tokens + embeddings (float4) ----
    if (tid < SEQ) s.toks[tid] = seqs[b * SEQ + tid];
    __syncthreads();
    {
        const float4* e4 = (const float4*)embed;
        float4* h4 = (float4*)s.h;
        #pragma unroll
        for (int r = 0; r < 4; r++) {
            int idx = tid + 128 * r;          // 0..511
            int t = idx >> 4, c = idx & 15;
            h4[idx] = e4[s.toks[t] * 16 + c];
        }
    }
    __syncthreads();

    // ---- encode: warp w handles tokens {w, w+4, ..., w+28}, paired (tk, tk+4) ----
    {
        // layer 1 (PACKED f32x2 over column pairs): lane owns cols [4*lane, 4*lane+4)
        const ulonglong2* w1_p = (const ulonglong2*)ffw1;
        ulonglong2 bbp = ((const ulonglong2*)ffb1)[lane];
        ull accL[8], accH[8];
        #pragma unroll
        for (int tk = 0; tk < 8; tk++) { accL[tk] = bbp.x; accH[tk] = bbp.y; }
        #pragma unroll 2
        for (int ib = 0; ib < Hd; ib += 4) {
            ulonglong2 wv0 = w1_p[(ib + 0) * 32 + lane];
            ulonglong2 wv1 = w1_p[(ib + 1) * 32 + lane];
            ulonglong2 wv2 = w1_p[(ib + 2) * 32 + lane];
            ulonglong2 wv3 = w1_p[(ib + 3) * 32 + lane];
            #pragma unroll
            for (int tk = 0; tk < 8; tk++) {
                float4 ev = *(const float4*)&s.h[(w + 4 * tk) * Hd + ib];
                ull e;
                PACKF2(e, ev.x, ev.x);
                FMAF2(accL[tk], e, wv0.x, accL[tk]);
                FMAF2(accH[tk], e, wv0.y, accH[tk]);
                PACKF2(e, ev.y, ev.y);
                FMAF2(accL[tk], e, wv1.x, accL[tk]);
                FMAF2(accH[tk], e, wv1.y, accH[tk]);
                PACKF2(e, ev.z, ev.z);
                FMAF2(accL[tk], e, wv2.x, accL[tk]);
                FMAF2(accH[tk], e, wv2.y, accH[tk]);
                PACKF2(e, ev.w, ev.w);
                FMAF2(accL[tk], e, wv3.x, accL[tk]);
                FMAF2(accH[tk], e, wv3.y, accH[tk]);
            }
        }
        // relu + store hidden INTERLEAVED over token pairs:
        // hpack[p][i] = (hid[tk=p][i], hid[tk=p+4][i]) at scratch[w*1024 + p*256 + 2*i]
        // lane owns i = 4*lane .. 4*lane+3  ->  floats [p*256 + 8*lane .. +8)
        #pragma unroll
        for (int p = 0; p < 4; p++) {
            float a0, a1_, a2_, a3, b0, b1_, b2_, b3;
            UNPACKF2(a0, a1_, accL[p]);
            UNPACKF2(a2_, a3, accH[p]);
            UNPACKF2(b0, b1_, accL[p + 4]);
            UNPACKF2(b2_, b3, accH[p + 4]);
            a0 = fmaxf(a0, 0.0f); a1_ = fmaxf(a1_, 0.0f);
            a2_ = fmaxf(a2_, 0.0f); a3 = fmaxf(a3, 0.0f);
            b0 = fmaxf(b0, 0.0f); b1_ = fmaxf(b1_, 0.0f);
            b2_ = fmaxf(b2_, 0.0f); b3 = fmaxf(b3, 0.0f);
            ull q0, q1, q2, q3;
            PACKF2(q0, a0, b0);
            PACKF2(q1, a1_, b1_);
            PACKF2(q2, a2_, b2_);
            PACKF2(q3, a3, b3);
            ulonglong2 s0; s0.x = q0; s0.y = q1;
            ulonglong2 s1; s1.x = q2; s1.y = q3;
            *(ulonglong2*)&s.scratch[w * 1024 + p * 256 + 8 * lane]     = s0;
            *(ulonglong2*)&s.scratch[w * 1024 + p * 256 + 8 * lane + 4] = s1;
        }
        __syncwarp();

        // layer 2 (PACKED f32x2 over token pairs): lane owns cols [2*lane, 2*lane+2)
        const float2* w2_2 = (const float2*)ffw2;
        float2 fb = ((const float2*)ffb2)[lane];
        ull acc2[4][2];
        {
            ull fbx, fby;
            PACKF2(fbx, fb.x, fb.x);
            PACKF2(fby, fb.y, fb.y);
            #pragma unroll
            for (int p = 0; p < 4; p++) { acc2[p][0] = fbx; acc2[p][1] = fby; }
        }
        #pragma unroll 2
        for (int ib = 0; ib < 2 * Hd; ib += 4) {
            float2 wv0 = w2_2[(ib + 0) * 32 + lane];
            float2 wv1 = w2_2[(ib + 1) * 32 + lane];
            float2 wv2 = w2_2[(ib + 2) * 32 + lane];
            float2 wv3 = w2_2[(ib + 3) * 32 + lane];
            ull w00, w01, w10, w11, w20, w21, w30, w31;
            PACKF2(w00, wv0.x, wv0.x); PACKF2(w01, wv0.y, wv0.y);
            PACKF2(w10, wv1.x, wv1.x); PACKF2(w11, wv1.y, wv1.y);
            PACKF2(w20, wv2.x, wv2.x); PACKF2(w21, wv2.y, wv2.y);
            PACKF2(w30, wv3.x, wv3.x); PACKF2(w31, wv3.y, wv3.y);
            #pragma unroll
            for (int p = 0; p < 4; p++) {
                ulonglong2 e01 = *(const ulonglong2*)&s.scratch[w * 1024 + p * 256 + 2 * ib];
                ulonglong2 e23 = *(const ulonglong2*)&s.scratch[w * 1024 + p * 256 + 2 * ib + 4];
                FMAF2(acc2[p][0], e01.x, w00, acc2[p][0]);
                FMAF2(acc2[p][1], e01.x, w01, acc2[p][1]);
                FMAF2(acc2[p][0], e01.y, w10, acc2[p][0]);
                FMAF2(acc2[p][1], e01.y, w11, acc2[p][1]);
                FMAF2(acc2[p][0], e23.x, w20, acc2[p][0]);
                FMAF2(acc2[p][1], e23.x, w21, acc2[p][1]);
                FMAF2(acc2[p][0], e23.y, w30, acc2[p][0]);
                FMAF2(acc2[p][1], e23.y, w31, acc2[p][1]);
            }
        }

        // unpack per-token f values: tk<4 -> lo lane of pair tk; tk>=4 -> hi lane of pair tk-4
        float2 fv[8];
        #pragma unroll
        for (int p = 0; p < 4; p++) {
            float l0, h0, l1, h1;
            UNPACKF2(l0, h0, acc2[p][0]);
            UNPACKF2(l1, h1, acc2[p][1]);
            fv[p]     = make_float2(l0, l1);
            fv[p + 4] = make_float2(h0, h1);
        }

        // residual + layernorm
        float2 g2  = ((const float2*)lng)[lane];
        float2 be2 = ((const float2*)lnb)[lane];
        float2* h2 = (float2*)s.h;
        #pragma unroll
        for (int tk = 0; tk < 8; tk++) {
            int t = w + 4 * tk;
            float2 x = h2[t * 32 + lane];
            x.x += fv[tk].x; x.y += fv[tk].y;
            float mean = wredsum(x.x + x.y) * (1.0f / 64.0f);
            float d0 = x.x - mean, d1 = x.y - mean;
            float var = wredsum(d0 * d0 + d1 * d1) * (1.0f / 64.0f);
            float rs = rsqrtf(var + 1e-5f);
            float2 r;
            r.x = fmaf(d0 * rs, g2.x, be2.x);
            r.y = fmaf(d1 * rs, g2.y, be2.y);
            h2[t * 32 + lane] = r;
        }
    }
    __syncthreads();

    // ---- scores (scratch dead from here; P/Vv/a1/... region live) ----
    for (int p = w; p < NPAIR; p += 4) {
        const float* kk = &s.h[(2 * p)     * Hd];
        const float* vv = &s.h[(2 * p + 1) * Hd];
        float acc = kk[lane]      * scw[lane]
                  + kk[lane + 32] * scw[lane + 32]
                  + vv[lane]      * scw[lane + 64]
                  + vv[lane + 32] * scw[lane + 96];
        acc = wredsum(acc);
        if (lane == 0) s.scores[p] = acc + scb[0];
    }
    __syncthreads();

    // ---- evict-min (thread 0) overlapped with P init + v zero (all) ----
    if (tid == 0) {
        #pragma unroll
        for (int i = 0; i < CAP; i++) { s.ord[i] = i; s.esc[i] = s.scores[i]; }
        for (int n = CAP; n < NPAIR; n++) {
            int mi = 0; float mv = s.esc[0];
            #pragma unroll
            for (int i = 1; i < CAP; i++) if (s.esc[i] < mv) { mv = s.esc[i]; mi = i; }
            for (int i = mi; i < CAP - 1; i++) { s.ord[i] = s.ord[i+1]; s.esc[i] = s.esc[i+1]; }
            s.ord[CAP-1] = n; s.esc[CAP-1] = s.scores[n];
        }
    }
    {
        float4* P4 = (float4*)s.P;
        float4* V4 = (float4*)s.Vv;
        for (int q = tid; q < 384; q += 128) P4[q]       = ((const float4*)mw1)[q];
        for (int q = tid; q < 384; q += 128) P4[390 + q] = ((const float4*)mw2)[q];
        if (tid < 6)  P4[384 + tid] = ((const float4*)mb1)[tid];
        if (tid >= 32 && tid < 48) P4[774 + (tid - 32)] = ((const float4*)mb2)[tid - 32];
        float4 z4 = make_float4(0.f, 0.f, 0.f, 0.f);
        for (int q = tid; q < 790; q += 128) V4[q] = z4;
    }
    __syncthreads();

    // per-thread constant index seeds for the w1 float4 update loop
    const int q0 = 4 * tid;
    const int j0 = q0 % 24;     // multiple of 4, row never crossed (24 % 4 == 0)
    const int i0 = q0 / 24;

    // packed Adam constants (m-path only)
    ull cB1, c01;
    PACKF2(cB1, B1c, B1c);
    PACKF2(c01, 0.1f, 0.1f);

    // ---- Adam m-state PACKED in registers; v-state in smem ----
    ull mW1L[3], mW1H[3], mW2L[3], mW2H[3];
    ull mBL = 0, mBH = 0;
    #pragma unroll
    for (int k = 0; k < 3; k++) {
        mW1L[k] = mW1H[k] = 0;
        mW2L[k] = mW2H[k] = 0;
    }

    // ---- 8 inner Adam steps ----
    float pb1 = 1.0f, pb2 = 1.0f;
    #pragma unroll 1
    for (int st = 0; st < CAP; st++) {
        pb1 *= B1c; pb2 *= B2c;
        float inv1 = __fdividef(1.0f, 1.0f - pb1);
        float s2   = sqrtf(1.0f - pb2);
        float negC = -LRc * inv1 * s2;
        float epsT = EPSc * s2;
        int koff = (s.ord[st] << 1) * Hd;
        int voff = koff + Hd;

        // fwd layer1: 96 threads, 4 lanes per j
        if (tid < 96) {
            const int j  = ((tid >> 5) << 3) + ((tid & 31) >> 2);
            const int sl = tid & 3;
            float acc = 0.0f;
            #pragma unroll
            for (int k = 0; k < 16; k++)
                acc = fmaf(s.h[koff + sl + 4 * k], s.P[(sl + 4 * k) * INNER + j], acc);
            acc += __shfl_xor_sync(0xffffffffu, acc, 1);
            acc += __shfl_xor_sync(0xffffffffu, acc, 2);
            if (sl == 0) s.a1[j] = fmaxf(acc + s.P[OFF_B1 + j], 0.0f);
        }
        __syncthreads();

        // fwd layer2 + output grad: 64 threads, 1 lane per o, conflict-free
        if (tid < 64) {
            const int o = tid;
            float accA = 0.0f, accB = 0.0f;
            #pragma unroll
            for (int k = 0; k < 12; k++) {
                accA = fmaf(s.a1[k],      s.P[OFF_W2 + k * Hd + o],        accA);
                accB = fmaf(s.a1[k + 12], s.P[OFF_W2 + (k + 12) * Hd + o], accB);
            }
            s.dout[o] = ((accA + accB) + s.P[OFF_B2 + o] - s.h[voff + o]) * 0.03125f;
        }
        __syncthreads();

        // backward into hidden: 96 threads, rotated conflict-free
        if (tid < 96) {
            const int j  = ((tid >> 5) << 3) + ((tid & 31) >> 2);
            const int sl = tid & 3;
            float acc = 0.0f;
            #pragma unroll
            for (int k = 0; k < 16; k++) {
                int o = sl + 4 * ((j + k) & 15);
                acc = fmaf(s.P[OFF_W2 + j * Hd + o], s.dout[o], acc);
            }
            acc += __shfl_xor_sync(0xffffffffu, acc, 1);
            acc += __shfl_xor_sync(0xffffffffu, acc, 2);
            if (sl == 0) s.dz1[j] = (s.a1[j] > 0.0f) ? acc : 0.0f;
        }
        __syncthreads();

        // parameter updates (float4 params, packed m in regs, v in smem)
        {
            float4* P4 = (float4*)s.P;
            float4* V4 = (float4*)s.Vv;
            // w1: quad (i*24 + j .. j+3), j multiple of 4 — incremental index
            int i = i0, j = j0;
            #pragma unroll
            for (int k = 0; k < 3; k++) {
                float hk = s.h[koff + i];
                ulonglong2 dzp = *(const ulonglong2*)&s.dz1[j];
                ull hk2, gL, gH;
                PACKF2(hk2, hk, hk);
                MULF2(gL, hk2, dzp.x);
                MULF2(gH, hk2, dzp.y);
                adam4s(P4, V4, tid + 128 * k, mW1L[k], mW1H[k],
                       gL, gH, negC, epsT, cB1, c01);
                j += 8; i += 21; if (j >= 24) { j -= 24; i += 1; }
            }
            // w2: quad (jj*64 + o .. o+3)
            #pragma unroll
            for (int k = 0; k < 3; k++) {
                int f = tid + 128 * k;
                float av = s.a1[f >> 4];
                ulonglong2 dvp = ((const ulonglong2*)s.dout)[f & 15];
                ull av2, gL, gH;
                PACKF2(av2, av, av);
                MULF2(gL, av2, dvp.x);
                MULF2(gH, av2, dvp.y);
                adam4s(P4, V4, 390 + f, mW2L[k], mW2H[k],
                       gL, gH, negC, epsT, cB1, c01);
            }
            // b1 (threads 0..5), b2 (threads 32..47) in parallel warps
            if (tid < 6) {
                ulonglong2 dzp = ((const ulonglong2*)s.dz1)[tid];
                adam4s(P4, V4, 384 + tid, mBL, mBH,
                       dzp.x, dzp.y, negC, epsT, cB1, c01);
            }
            if (tid >= 32 && tid < 48) {
                ulonglong2 dvp = ((const ulonglong2*)s.dout)[tid - 32];
                adam4s(P4, V4, 774 + (tid - 32), mBL, mBH,
                       dvp.x, dvp.y, negC, epsT, cB1, c01);
            }
        }
        __syncthreads();
    }

    // ---- query through finetuned MLP + output head ----
    {
        const int qoff = (SEQ - 2) * Hd;
        if (tid < 96) {
            const int j  = ((tid >> 5) << 3) + ((tid & 31) >> 2);
            const int sl = tid & 3;
            float acc = 0.0f;
            #pragma unroll
            for (int k = 0; k < 16; k++)
                acc = fmaf(s.h[qoff + sl + 4 * k], s.P[(sl + 4 * k) * INNER + j], acc);
            acc += __shfl_xor_sync(0xffffffffu, acc, 1);
            acc += __shfl_xor_sync(0xffffffffu, acc, 2);
            if (sl == 0) s.a1[j] = fmaxf(acc + s.P[OFF_B1 + j], 0.0f);
        }
        __syncthreads();
        if (tid < 64) {
            const int o = tid;
            float accA = 0.0f, accB = 0.0f;
            #pragma unroll
            for (int k = 0; k < 12; k++) {
                accA = fmaf(s.a1[k],      s.P[OFF_W2 + k * Hd + o],        accA);
                accB = fmaf(s.a1[k + 12], s.P[OFF_W2 + (k + 12) * Hd + o], accB);
            }
            s.dout[o] = (accA + accB) + s.P[OFF_B2 + o];
        }
        __syncthreads();
        if (tid < Vd) {
            float acc = outb[tid];
            #pragma unroll 8
            for (int o = 0; o < Hd; o++)
                acc = fmaf(s.dout[o], outw[o * Vd + tid], acc);
            out[b * Vd + tid] = acc;
        }
    }
}

extern "C" void kernel_launch(void* const* d_in, const int* in_sizes, int n_in,
                              void* d_out, int out_size) {
    const int*   seqs  = (const int*)  d_in[0];
    const float* embed = (const float*)d_in[1];
    const float* ffw1  = (const float*)d_in[2];
    const float* ffb1  = (const float*)d_in[3];
    const float* ffw2  = (const float*)d_in[4];
    const float* ffb2  = (const float*)d_in[5];
    const float* lng   = (const float*)d_in[6];
    const float* lnb   = (const float*)d_in[7];
    const float* scw   = (const float*)d_in[8];
    const float* scb   = (const float*)d_in[9];
    const float* mw1   = (const float*)d_in[10];
    const float* mb1   = (const float*)d_in[11];
    const float* mw2   = (const float*)d_in[12];
    const float* mb2   = (const float*)d_in[13];
    const float* outw  = (const float*)d_in[14];
    const float* outb  = (const float*)d_in[15];
    float* out = (float*)d_out;

    int B = in_sizes[0] / SEQ;
    ttt_kernel<<<B, 128>>>(seqs, embed, ffw1, ffb1, ffw2, ffb2, lng, lnb,
                           scw, scb, mw1, mb1, mw2, mb2, outw, outb, out);
}

// round 17
// speedup vs baseline: 1.2602x; 1.0041x over previous
#include <cuda_runtime.h>

#define Hd 64
#define Vd 64
#define INNER 24
#define SEQ 32
#define CAP 8
#define NPAIR 15
#define LRc 0.05f
#define B1c 0.9f
#define B2c 0.999f
#define EPSc 1e-8f

#define NW1 (Hd*INNER)             // 1536
#define OFF_B1 NW1                 // 1536
#define OFF_W2 (NW1 + INNER)       // 1560
#define OFF_B2 (OFF_W2 + INNER*Hd) // 3096
#define NPARAM (OFF_B2 + Hd)       // 3160
#define EOFF 4096                  // float offset of embed-pack region in scratch

typedef unsigned long long ull;

// Packed fp32x2 ops (sm_103a FFMA2 path — per-lane IEEE fp32, bit-identical)
#define PACKF2(d, lo, hi) asm("mov.b64 %0, {%1, %2};" : "=l"(d) : "f"(lo), "f"(hi))
#define UNPACKF2(lo, hi, s) asm("mov.b64 {%0, %1}, %2;" : "=f"(lo), "=f"(hi) : "l"(s))
#define FMAF2(d, a, b, c) asm("fma.rn.f32x2 %0, %1, %2, %3;" : "=l"(d) : "l"(a), "l"(b), "l"(c))
#define MULF2(d, a, b) asm("mul.rn.f32x2 %0, %1, %2;" : "=l"(d) : "l"(a), "l"(b))

struct __align__(16) SmemLayout {
    float h[SEQ*Hd];               // 2048 floats (8KB)
    union {
        // encode-only: [0,4096) hidden acts (4 warps x 1024),
        //              [4096,6144) token-pair-interleaved embeddings (4 warps x 512)
        float scratch[6144];
        struct {
            float P[NPARAM];       // params  w1[i*24+j] | b1 | w2[j*64+o] | b2 (12640B)
            float Vv[NPARAM];      // Adam v (smem; m stays in registers)
            float a1[INNER];       // 16B-aligned
            float dz1[INNER];
            float dout[Hd];
            float scores[NPAIR + 1];
            float esc[CAP];
            int   ord[CAP];
            int   toks[SEQ];       // only live before encode (pre-scratch)
        };
    };
};

__device__ __forceinline__ float wredsum(float x) {
    #pragma unroll
    for (int o = 16; o; o >>= 1) x += __shfl_xor_sync(0xffffffffu, x, o);
    return x;
}

// Exact eps-folded Adam on a quad; m PACKED in registers, v in smem, params in smem.
// Per-component op order identical to prior rounds (bit-identical):
//   m = fma(B1, m, 0.1*g);  v = fma(B2, v, (0.001*g)*g)
//   s = max(v*rsqrt(v), 0); p += negC * (m / (s + epsT))
__device__ __forceinline__ void adam4s(float4* __restrict__ P4, float4* __restrict__ V4,
                                       int f, ull& mL, ull& mH,
                                       ull gL, ull gH, float negC, float epsT,
                                       ull cB1, ull c01) {
    ull t;
    MULF2(t, c01, gL);  FMAF2(mL, cB1, mL, t);
    MULF2(t, c01, gH);  FMAF2(mH, cB1, mH, t);
    float g0, g1, g2, g3;
    UNPACKF2(g0, g1, gL); UNPACKF2(g2, g3, gH);
    float4 v = V4[f];
    v.x = fmaf(B2c, v.x, (0.001f * g0) * g0);
    v.y = fmaf(B2c, v.y, (0.001f * g1) * g1);
    v.z = fmaf(B2c, v.z, (0.001f * g2) * g2);
    v.w = fmaf(B2c, v.w, (0.001f * g3) * g3);
    V4[f] = v;
    float m0, m1, m2, m3;
    UNPACKF2(m0, m1, mL); UNPACKF2(m2, m3, mH);
    float s0 = fmaxf(v.x * __frsqrt_rn(v.x), 0.0f);
    float s1 = fmaxf(v.y * __frsqrt_rn(v.y), 0.0f);
    float s2_ = fmaxf(v.z * __frsqrt_rn(v.z), 0.0f);
    float s3 = fmaxf(v.w * __frsqrt_rn(v.w), 0.0f);
    float4 p = P4[f];
    p.x = fmaf(negC, __fdividef(m0, s0 + epsT), p.x);
    p.y = fmaf(negC, __fdividef(m1, s1 + epsT), p.y);
    p.z = fmaf(negC, __fdividef(m2, s2_ + epsT), p.z);
    p.w = fmaf(negC, __fdividef(m3, s3 + epsT), p.w);
    P4[f] = p;
}

__global__ void __launch_bounds__(128, 6) ttt_kernel(
    const int*   __restrict__ seqs,
    const float* __restrict__ embed,
    const float* __restrict__ ffw1, const float* __restrict__ ffb1,
    const float* __restrict__ ffw2, const float* __restrict__ ffb2,
    const float* __restrict__ lng,  const float* __restrict__ lnb,
    const float* __restrict__ scw,  const float* __restrict__ scb,
    const float* __restrict__ mw1,  const float* __restrict__ mb1,
    const float* __restrict__ mw2,  const float* __restrict__ mb2,
    const float* __restrict__ outw, const float* __restrict__ outb,
    float* __restrict__ out)
{
    __shared__ SmemLayout s;
    const int tid  = threadIdx.x;
    const int lane = tid & 31;
    const int w    = tid >> 5;
    const int b    = blockIdx.x;

    // ---- tokens + embeddings (float4) + token-pair-interleaved staging ----
    // pair p of warp ww pairs tokens t1 = ww+4p and t2 = ww+4p+16 (tk=p, tk=p+4).
    // epack float layout: EOFF + ww*512 + p*128 + 2*i + half, half = tk>>2.
    if (tid < SEQ) s.toks[tid] = seqs[b * SEQ + tid];
    __syncthreads();
    {
        const float4* e4 = (const float4*)embed;
        float4* h4 = (float4*)s.h;
        #pragma unroll
        for (int r = 0; r < 4; r++) {
            int idx = tid + 128 * r;          // 0..511
            int t = idx >> 4, c = idx & 15;
            float4 ev = e4[s.toks[t] * 16 + c];
            h4[idx] = ev;
            int ww = t & 3, tk = t >> 2;
            int p = tk & 3, half = tk >> 2;
            float* eb = &s.scratch[EOFF + ww * 512 + p * 128 + 8 * c + half];
            eb[0] = ev.x; eb[2] = ev.y; eb[4] = ev.z; eb[6] = ev.w;
        }
    }
    __syncthreads();

    // ---- encode: warp w handles tokens {w, w+4, ..., w+28}, paired (tk, tk+4) ----
    {
        // layer 1 (PACKED f32x2 over TOKEN pairs, pre-packed embeds):
        // lane owns cols [4*lane, 4*lane+4); acc[p][c] = (hid[tk=p][c'], hid[tk=p+4][c'])
        const float4* w1f = (const float4*)ffw1;
        float4 bb = ((const float4*)ffb1)[lane];
        ull acc[4][4];
        {
            ull b0, b1_, b2_, b3;
            PACKF2(b0, bb.x, bb.x); PACKF2(b1_, bb.y, bb.y);
            PACKF2(b2_, bb.z, bb.z); PACKF2(b3, bb.w, bb.w);
            #pragma unroll
            for (int p = 0; p < 4; p++) {
                acc[p][0] = b0; acc[p][1] = b1_; acc[p][2] = b2_; acc[p][3] = b3;
            }
        }
        const ulonglong2* ep = (const ulonglong2*)&s.scratch[EOFF + w * 512];
        #pragma unroll 2
        for (int ib = 0; ib < Hd; ib += 2) {
            float4 wr0 = w1f[(ib + 0) * 32 + lane];
            float4 wr1 = w1f[(ib + 1) * 32 + lane];
            ull w00, w01, w02, w03, w10, w11, w12, w13;
            PACKF2(w00, wr0.x, wr0.x); PACKF2(w01, wr0.y, wr0.y);
            PACKF2(w02, wr0.z, wr0.z); PACKF2(w03, wr0.w, wr0.w);
            PACKF2(w10, wr1.x, wr1.x); PACKF2(w11, wr1.y, wr1.y);
            PACKF2(w12, wr1.z, wr1.z); PACKF2(w13, wr1.w, wr1.w);
            #pragma unroll
            for (int p = 0; p < 4; p++) {
                ulonglong2 e2 = ep[p * 32 + (ib >> 1)];  // (epack[i=ib], epack[i=ib+1])
                FMAF2(acc[p][0], e2.x, w00, acc[p][0]);
                FMAF2(acc[p][1], e2.x, w01, acc[p][1]);
                FMAF2(acc[p][2], e2.x, w02, acc[p][2]);
                FMAF2(acc[p][3], e2.x, w03, acc[p][3]);
                FMAF2(acc[p][0], e2.y, w10, acc[p][0]);
                FMAF2(acc[p][1], e2.y, w11, acc[p][1]);
                FMAF2(acc[p][2], e2.y, w12, acc[p][2]);
                FMAF2(acc[p][3], e2.y, w13, acc[p][3]);
            }
        }
        // relu + store hidden INTERLEAVED over token pairs (already packed):
        // hpack[p][i'] at scratch[w*1024 + p*256 + 2*i'], i' = 4*lane + c
        #pragma unroll
        for (int p = 0; p < 4; p++) {
            ull q[4];
            #pragma unroll
            for (int c = 0; c < 4; c++) {
                float lo, hi;
                UNPACKF2(lo, hi, acc[p][c]);
                lo = fmaxf(lo, 0.0f); hi = fmaxf(hi, 0.0f);
                PACKF2(q[c], lo, hi);
            }
            ulonglong2 s0; s0.x = q[0]; s0.y = q[1];
            ulonglong2 s1; s1.x = q[2]; s1.y = q[3];
            *(ulonglong2*)&s.scratch[w * 1024 + p * 256 + 8 * lane]     = s0;
            *(ulonglong2*)&s.scratch[w * 1024 + p * 256 + 8 * lane + 4] = s1;
        }
        __syncwarp();

        // layer 2 (PACKED f32x2 over token pairs): lane owns cols [2*lane, 2*lane+2)
        const float2* w2_2 = (const float2*)ffw2;
        float2 fb = ((const float2*)ffb2)[lane];
        ull acc2[4][2];
        {
            ull fbx, fby;
            PACKF2(fbx, fb.x, fb.x);
            PACKF2(fby, fb.y, fb.y);
            #pragma unroll
            for (int p = 0; p < 4; p++) { acc2[p][0] = fbx; acc2[p][1] = fby; }
        }
        #pragma unroll 2
        for (int ib = 0; ib < 2 * Hd; ib += 4) {
            float2 wv0 = w2_2[(ib + 0) * 32 + lane];
            float2 wv1 = w2_2[(ib + 1) * 32 + lane];
            float2 wv2 = w2_2[(ib + 2) * 32 + lane];
            float2 wv3 = w2_2[(ib + 3) * 32 + lane];
            ull w00, w01, w10, w11, w20, w21, w30, w31;
            PACKF2(w00, wv0.x, wv0.x); PACKF2(w01, wv0.y, wv0.y);
            PACKF2(w10, wv1.x, wv1.x); PACKF2(w11, wv1.y, wv1.y);
            PACKF2(w20, wv2.x, wv2.x); PACKF2(w21, wv2.y, wv2.y);
            PACKF2(w30, wv3.x, wv3.x); PACKF2(w31, wv3.y, wv3.y);
            #pragma unroll
            for (int p = 0; p < 4; p++) {
                ulonglong2 e01 = *(const ulonglong2*)&s.scratch[w * 1024 + p * 256 + 2 * ib];
                ulonglong2 e23 = *(const ulonglong2*)&s.scratch[w * 1024 + p * 256 + 2 * ib + 4];
                FMAF2(acc2[p][0], e01.x, w00, acc2[p][0]);
                FMAF2(acc2[p][1], e01.x, w01, acc2[p][1]);
                FMAF2(acc2[p][0], e01.y, w10, acc2[p][0]);
                FMAF2(acc2[p][1], e01.y, w11, acc2[p][1]);
                FMAF2(acc2[p][0], e23.x, w20, acc2[p][0]);
                FMAF2(acc2[p][1], e23.x, w21, acc2[p][1]);
                FMAF2(acc2[p][0], e23.y, w30, acc2[p][0]);
                FMAF2(acc2[p][1], e23.y, w31, acc2[p][1]);
            }
        }

        // unpack per-token f values: tk<4 -> lo lane of pair tk; tk>=4 -> hi lane of pair tk-4
        float2 fv[8];
        #pragma unroll
        for (int p = 0; p < 4; p++) {
            float l0, h0, l1, h1;
            UNPACKF2(l0, h0, acc2[p][0]);
            UNPACKF2(l1, h1, acc2[p][1]);
            fv[p]     = make_float2(l0, l1);
            fv[p + 4] = make_float2(h0, h1);
        }

        // residual + layernorm
        float2 g2  = ((const float2*)lng)[lane];
        float2 be2 = ((const float2*)lnb)[lane];
        float2* h2 = (float2*)s.h;
        #pragma unroll
        for (int tk = 0; tk < 8; tk++) {
            int t = w + 4 * tk;
            float2 x = h2[t * 32 + lane];
            x.x += fv[tk].x; x.y += fv[tk].y;
            float mean = wredsum(x.x + x.y) * (1.0f / 64.0f);
            float d0 = x.x - mean, d1 = x.y - mean;
            float var = wredsum(d0 * d0 + d1 * d1) * (1.0f / 64.0f);
            float rs = rsqrtf(var + 1e-5f);
            float2 r;
            r.x = fmaf(d0 * rs, g2.x, be2.x);
            r.y = fmaf(d1 * rs, g2.y, be2.y);
            h2[t * 32 + lane] = r;
        }
    }
    __syncthreads();

    // ---- scores (scratch dead from here; P/Vv/a1/... region live) ----
    for (int p = w; p < NPAIR; p += 4) {
        const float* kk = &s.h[(2 * p)     * Hd];
        const float* vv = &s.h[(2 * p + 1) * Hd];
        float acc = kk[lane]      * scw[lane]
                  + kk[lane + 32] * scw[lane + 32]
                  + vv[lane]      * scw[lane + 64]
                  + vv[lane + 32] * scw[lane + 96];
        acc = wredsum(acc);
        if (lane == 0) s.scores[p] = acc + scb[0];
    }
    __syncthreads();

    // ---- evict-min (thread 0) overlapped with P init + v zero (all) ----
    if (tid == 0) {
        #pragma unroll
        for (int i = 0; i < CAP; i++) { s.ord[i] = i; s.esc[i] = s.scores[i]; }
        for (int n = CAP; n < NPAIR; n++) {
            int mi = 0; float mv = s.esc[0];
            #pragma unroll
            for (int i = 1; i < CAP; i++) if (s.esc[i] < mv) { mv = s.esc[i]; mi = i; }
            for (int i = mi; i < CAP - 1; i++) { s.ord[i] = s.ord[i+1]; s.esc[i] = s.esc[i+1]; }
            s.ord[CAP-1] = n; s.esc[CAP-1] = s.scores[n];
        }
    }
    {
        float4* P4 = (float4*)s.P;
        float4* V4 = (float4*)s.Vv;
        for (int q = tid; q < 384; q += 128) P4[q]       = ((const float4*)mw1)[q];
        for (int q = tid; q < 384; q += 128) P4[390 + q] = ((const float4*)mw2)[q];
        if (tid < 6)  P4[384 + tid] = ((const float4*)mb1)[tid];
        if (tid >= 32 && tid < 48) P4[774 + (tid - 32)] = ((const float4*)mb2)[tid - 32];
        float4 z4 = make_float4(0.f, 0.f, 0.f, 0.f);
        for (int q = tid; q < 790; q += 128) V4[q] = z4;
    }
    __syncthreads();

    // per-thread constant index seeds for the w1 float4 update loop
    const int q0 = 4 * tid;
    const int j0 = q0 % 24;     // multiple of 4, row never crossed (24 % 4 == 0)
    const int i0 = q0 / 24;

    // packed Adam constants (m-path only)
    ull cB1, c01;
    PACKF2(cB1, B1c, B1c);
    PACKF2(c01, 0.1f, 0.1f);

    // ---- Adam m-state PACKED in registers; v-state in smem ----
    ull mW1L[3], mW1H[3], mW2L[3], mW2H[3];
    ull mBL = 0, mBH = 0;
    #pragma unroll
    for (int k = 0; k < 3; k++) {
        mW1L[k] = mW1H[k] = 0;
        mW2L[k] = mW2H[k] = 0;
    }

    // ---- 8 inner Adam steps ----
    float pb1 = 1.0f, pb2 = 1.0f;
    #pragma unroll 1
    for (int st = 0; st < CAP; st++) {
        pb1 *= B1c; pb2 *= B2c;
        float inv1 = __fdividef(1.0f, 1.0f - pb1);
        float s2   = sqrtf(1.0f - pb2);
        float negC = -LRc * inv1 * s2;
        float epsT = EPSc * s2;
        int koff = (s.ord[st] << 1) * Hd;
        int voff = koff + Hd;

        // fwd layer1: 96 threads, 4 lanes per j
        if (tid < 96) {
            const int j  = ((tid >> 5) << 3) + ((tid & 31) >> 2);
            const int sl = tid & 3;
            float acc = 0.0f;
            #pragma unroll
            for (int k = 0; k < 16; k++)
                acc = fmaf(s.h[koff + sl + 4 * k], s.P[(sl + 4 * k) * INNER + j], acc);
            acc += __shfl_xor_sync(0xffffffffu, acc, 1);
            acc += __shfl_xor_sync(0xffffffffu, acc, 2);
            if (sl == 0) s.a1[j] = fmaxf(acc + s.P[OFF_B1 + j], 0.0f);
        }
        __syncthreads();

        // fwd layer2 + output grad: 64 threads, 1 lane per o, conflict-free
        if (tid < 64) {
            const int o = tid;
            float accA = 0.0f, accB = 0.0f;
            #pragma unroll
            for (int k = 0; k < 12; k++) {
                accA = fmaf(s.a1[k],      s.P[OFF_W2 + k * Hd + o],        accA);
                accB = fmaf(s.a1[k + 12], s.P[OFF_W2 + (k + 12) * Hd + o], accB);
            }
            s.dout[o] = ((accA + accB) + s.P[OFF_B2 + o] - s.h[voff + o]) * 0.03125f;
        }
        __syncthreads();

        // backward into hidden: 96 threads, rotated conflict-free
        if (tid < 96) {
            const int j  = ((tid >> 5) << 3) + ((tid & 31) >> 2);
            const int sl = tid & 3;
            float acc = 0.0f;
            #pragma unroll
            for (int k = 0; k < 16; k++) {
                int o = sl + 4 * ((j + k) & 15);
                acc = fmaf(s.P[OFF_W2 + j * Hd + o], s.dout[o], acc);
            }
            acc += __shfl_xor_sync(0xffffffffu, acc, 1);
            acc += __shfl_xor_sync(0xffffffffu, acc, 2);
            if (sl == 0) s.dz1[j] = (s.a1[j] > 0.0f) ? acc : 0.0f;
        }
        __syncthreads();

        // parameter updates (float4 params, packed m in regs, v in smem)
        {
            float4* P4 = (float4*)s.P;
            float4* V4 = (float4*)s.Vv;
            // w1: quad (i*24 + j .. j+3), j multiple of 4 — incremental index
            int i = i0, j = j0;
            #pragma unroll
            for (int k = 0; k < 3; k++) {
                float hk = s.h[koff + i];
                ulonglong2 dzp = *(const ulonglong2*)&s.dz1[j];
                ull hk2, gL, gH;
                PACKF2(hk2, hk, hk);
                MULF2(gL, hk2, dzp.x);
                MULF2(gH, hk2, dzp.y);
                adam4s(P4, V4, tid + 128 * k, mW1L[k], mW1H[k],
                       gL, gH, negC, epsT, cB1, c01);
                j += 8; i += 21; if (j >= 24) { j -= 24; i += 1; }
            }
            // w2: quad (jj*64 + o .. o+3)
            #pragma unroll
            for (int k = 0; k < 3; k++) {
                int f = tid + 128 * k;
                float av = s.a1[f >> 4];
                ulonglong2 dvp = ((const ulonglong2*)s.dout)[f & 15];
                ull av2, gL, gH;
                PACKF2(av2, av, av);
                MULF2(gL, av2, dvp.x);
                MULF2(gH, av2, dvp.y);
                adam4s(P4, V4, 390 + f, mW2L[k], mW2H[k],
                       gL, gH, negC, epsT, cB1, c01);
            }
            // b1 (threads 0..5), b2 (threads 32..47) in parallel warps
            if (tid < 6) {
                ulonglong2 dzp = ((const ulonglong2*)s.dz1)[tid];
                adam4s(P4, V4, 384 + tid, mBL, mBH,
                       dzp.x, dzp.y, negC, epsT, cB1, c01);
            }
            if (tid >= 32 && tid < 48) {
                ulonglong2 dvp = ((const ulonglong2*)s.dout)[tid - 32];
                adam4s(P4, V4, 774 + (tid - 32), mBL, mBH,
                       dvp.x, dvp.y, negC, epsT, cB1, c01);
            }
        }
        __syncthreads();
    }

    // ---- query through finetuned MLP + output head ----
    {
        const int qoff = (SEQ - 2) * Hd;
        if (tid < 96) {
            const int j  = ((tid >> 5) << 3) + ((tid & 31) >> 2);
            const int sl = tid & 3;
            float acc = 0.0f;
            #pragma unroll
            for (int k = 0; k < 16; k++)
                acc = fmaf(s.h[qoff + sl + 4 * k], s.P[(sl + 4 * k) * INNER + j], acc);
            acc += __shfl_xor_sync(0xffffffffu, acc, 1);
            acc += __shfl_xor_sync(0xffffffffu, acc, 2);
            if (sl == 0) s.a1[j] = fmaxf(acc + s.P[OFF_B1 + j], 0.0f);
        }
        __syncthreads();
        if (tid < 64) {
            const int o = tid;
            float accA = 0.0f, accB = 0.0f;
            #pragma unroll
            for (int k = 0; k < 12; k++) {
                accA = fmaf(s.a1[k],      s.P[OFF_W2 + k * Hd + o],        accA);
                accB = fmaf(s.a1[k + 12], s.P[OFF_W2 + (k + 12) * Hd + o], accB);
            }
            s.dout[o] = (accA + accB) + s.P[OFF_B2 + o];
        }
        __syncthreads();
        if (tid < Vd) {
            float acc = outb[tid];
            #pragma unroll 8
            for (int o = 0; o < Hd; o++)
                acc = fmaf(s.dout[o], outw[o * Vd + tid], acc);
            out[b * Vd + tid] = acc;
        }
    }
}

extern "C" void kernel_launch(void* const* d_in, const int* in_sizes, int n_in,
                              void* d_out, int out_size) {
    const int*   seqs  = (const int*)  d_in[0];
    const float* embed = (const float*)d_in[1];
    const float* ffw1  = (const float*)d_in[2];
    const float* ffb1  = (const float*)d_in[3];
    const float* ffw2  = (const float*)d_in[4];
    const float* ffb2  = (const float*)d_in[5];
    const float* lng   = (const float*)d_in[6];
    const float* lnb   = (const float*)d_in[7];
    const float* scw   = (const float*)d_in[8];
    const float* scb   = (const float*)d_in[9];
    const float* mw1   = (const float*)d_in[10];
    const float* mb1   = (const float*)d_in[11];
    const float* mw2   = (const float*)d_in[12];
    const float* mb2   = (const float*)d_in[13];
    const float* outw  = (const float*)d_in[14];
    const float* outb  = (const float*)d_in[15];
    float* out = (float*)d_out;

    int B = in_sizes[0] / SEQ;
    ttt_kernel<<<B, 128>>>(seqs, embed, ffw1, ffb1, ffw2, ffb2, lng, lnb,
                           scw, scb, mw1, mb1, mw2, mb2, outw, outb, out);
}